// round 7
// baseline (speedup 1.0000x reference)
#include <cuda_runtime.h>
#include <cstdint>

#define S_LEN 2048
#define D_DIM 1024
#define BATCH 4
#define MTOT  (BATCH * S_LEN)   // 8192

// ============================ device scratch ================================
__device__ int8_t g_xq1[(size_t)MTOT * D_DIM];
__device__ int8_t g_xq0[(size_t)MTOT * D_DIM];
__device__ int8_t g_wq1[(size_t)3 * D_DIM * D_DIM];   // W^T digits (q,k,v)
__device__ int8_t g_wq0[(size_t)3 * D_DIM * D_DIM];
__device__ float  g_qf [(size_t)MTOT * D_DIM];
__device__ float  g_kf [(size_t)MTOT * D_DIM];
__device__ float  g_vf [(size_t)MTOT * D_DIM];
__device__ int8_t g_qq1[(size_t)MTOT * D_DIM];
__device__ int8_t g_qq0[(size_t)MTOT * D_DIM];
__device__ int8_t g_kq1[(size_t)MTOT * D_DIM];
__device__ int8_t g_kq0[(size_t)MTOT * D_DIM];
__device__ int8_t g_vt1[(size_t)BATCH * D_DIM * S_LEN];  // V^T digits per batch
__device__ int8_t g_vt0[(size_t)BATCH * D_DIM * S_LEN];
__device__ float  g_sc [(size_t)BATCH * S_LEN * S_LEN];
__device__ int8_t g_sw1[(size_t)BATCH * S_LEN * S_LEN];  // softmax weight digits
__device__ int8_t g_sw0[(size_t)BATCH * S_LEN * S_LEN];
// per-row scales
__device__ float g_sx  [MTOT];
__device__ float g_swsc[3 * D_DIM];
__device__ float g_sq  [MTOT];
__device__ float g_sk  [MTOT];
__device__ float g_svt [BATCH * D_DIM];
__device__ float g_ssw [MTOT];

// ============================ PTX helpers ===================================
__device__ __forceinline__ uint32_t smem_u32(const void* p) {
    uint32_t a;
    asm("{ .reg .u64 t; cvta.to.shared.u64 t, %1; cvt.u32.u64 %0, t; }" : "=r"(a) : "l"(p));
    return a;
}
__device__ __forceinline__ void cp16(uint32_t s, const void* g) {
    asm volatile("cp.async.cg.shared.global [%0], [%1], 16;" :: "r"(s), "l"(g) : "memory");
}
#define CP_COMMIT() asm volatile("cp.async.commit_group;" ::: "memory")
#define CP_WAIT(n)  asm volatile("cp.async.wait_group %0;" :: "n"(n) : "memory")

__device__ __forceinline__ void ldm4(uint32_t r[4], uint32_t a) {
    asm volatile("ldmatrix.sync.aligned.m8n8.x4.shared.b16 {%0,%1,%2,%3}, [%4];"
                 : "=r"(r[0]), "=r"(r[1]), "=r"(r[2]), "=r"(r[3]) : "r"(a));
}
// int8 MMA: D[16,8] s32 += A[16,32] s8 * B[32,8] s8
__device__ __forceinline__ void mma_s8(int c[4], const uint32_t a[4], const uint32_t b[2]) {
    asm volatile("mma.sync.aligned.m16n8k32.row.col.s32.s8.s8.s32 "
                 "{%0,%1,%2,%3}, {%4,%5,%6,%7}, {%8,%9}, {%0,%1,%2,%3};"
                 : "+r"(c[0]), "+r"(c[1]), "+r"(c[2]), "+r"(c[3])
                 : "r"(a[0]), "r"(a[1]), "r"(a[2]), "r"(a[3]), "r"(b[0]), "r"(b[1]));
}

// quantize x -> a1*128 + a0, q in [-16256, 16256]
__device__ __forceinline__ void quant1(float x, float inv, int& a1, int& a0) {
    float q = rintf(x * inv);
    a1 = (int)rintf(q * 0.0078125f);
    a0 = (int)q - (a1 << 7);
}

// ====================== split-int8 IMMA GEMM ================================
// C[M,N] = sA[m]*sB[n] * (16384*A1B1 + 128*(A1B0+A0B1))   (a0b0 dropped, 2^-14)
// CTA 128x64xBK64, 128 threads, 4 warps (2m x 2n), warp 64x32, 2 CTAs/SM.
// XOR chunk swizzle on 64B rows: phys_chunk = c ^ ((row>>1)&3).
// s8-k32 ldmatrix addressing is byte-identical to the verified bf16-k16 layout.
constexpr int ROW_B  = 64;                 // 64 int8 per row
constexpr int A_B    = 128 * ROW_B;        // 8192 B per A digit tile
constexpr int B_B    = 64 * ROW_B;         // 4096 B per B digit tile
constexpr int STG_B  = 2 * A_B + 2 * B_B;  // 24576 B
constexpr int NSTG   = 4;
constexpr int SMEM_SZ = NSTG * STG_B;      // 98304 B -> 2 CTAs/SM (192KB)

__device__ __forceinline__ void load_stage(uint32_t base,
    const int8_t* __restrict__ a1, const int8_t* __restrict__ a0,
    const int8_t* __restrict__ b1, const int8_t* __restrict__ b0,
    int bm, int bn, int kt, int K, int tid)
{
    const int r  = tid >> 2;               // 0..31
    const int c  = tid & 3;                // logical 16B chunk
    const int kc = kt * 64 + c * 16;
    const int cp = c ^ ((r >> 1) & 3);     // swizzle, invariant to +32 rows
#pragma unroll
    for (int g = 0; g < 4; g++) {
        const int row = r + g * 32;
        const uint32_t so = (uint32_t)row * ROW_B + cp * 16;
        const long ga = (long)(bm + row) * K + kc;
        cp16(base + so,       a1 + ga);
        cp16(base + A_B + so, a0 + ga);
        if (g < 2) {
            const long gb = (long)(bn + row) * K + kc;
            cp16(base + 2 * A_B + so,       b1 + gb);
            cp16(base + 2 * A_B + B_B + so, b0 + gb);
        }
    }
}

// FUSED=1: z in {0,1,2} selects output C0/C1/C2 (QKV projection)
// FUSED=0: C = C0 + z*sC (batched attention GEMMs)
template <int FUSED>
__global__ void __launch_bounds__(128, 2)
gemm_i8(const int8_t* __restrict__ Ag1, const int8_t* __restrict__ Ag0,
        const int8_t* __restrict__ Bg1, const int8_t* __restrict__ Bg0,
        const float* __restrict__ sA, const float* __restrict__ sB,
        long sAz, long sBz,
        float* __restrict__ C0, float* __restrict__ C1, float* __restrict__ C2,
        int N, int K, long sA_, long sB_, long sC)
{
    extern __shared__ __align__(128) char smem[];
    const uint32_t sb = smem_u32(smem);
    const int tid = threadIdx.x, lane = tid & 31, warp = tid >> 5;
    const int wm = warp >> 1, wn = warp & 1;          // 2 x 2 warps, 64x32 tiles
    const int bm = blockIdx.y * 128, bn = blockIdx.x * 64, z = blockIdx.z;

    const int8_t* A1 = Ag1 + (long)z * sA_;
    const int8_t* A0 = Ag0 + (long)z * sA_;
    const int8_t* B1 = Bg1 + (long)z * sB_;
    const int8_t* B0 = Bg0 + (long)z * sB_;

    const int nk = K >> 6;   // K per stage = 64

    // ldmatrix per-thread components (identical mapping to verified bf16 path)
    const uint32_t aRow = (uint32_t)(wm * 64 + (lane & 15));
    const uint32_t aSw  = (aRow >> 1) & 3;
    const uint32_t aC0  = (uint32_t)((lane >> 4) & 1);
    const uint32_t bRow0 = (uint32_t)((lane & 7) | (((lane >> 4) & 1) << 3));
    const uint32_t bRow = (uint32_t)(wn * 32) + bRow0;
    const uint32_t bSw  = (bRow0 >> 1) & 3;
    const uint32_t bC0  = (uint32_t)((lane >> 3) & 1);

    int acc1[4][4][4], acc2[4][4][4];
#pragma unroll
    for (int i = 0; i < 4; i++)
#pragma unroll
        for (int j = 0; j < 4; j++)
#pragma unroll
            for (int q = 0; q < 4; q++) { acc1[i][j][q] = 0; acc2[i][j][q] = 0; }

    // prologue: NSTG-1 stages in flight
#pragma unroll
    for (int s = 0; s < NSTG - 1; s++) {
        load_stage(sb + s * STG_B, A1, A0, B1, B0, bm, bn, s, K, tid);
        CP_COMMIT();
    }

    for (int kt = 0; kt < nk; kt++) {
        CP_WAIT(NSTG - 2);
        __syncthreads();

        const int nx = kt + NSTG - 1;
        if (nx < nk)
            load_stage(sb + (nx % NSTG) * STG_B, A1, A0, B1, B0, bm, bn, nx, K, tid);
        CP_COMMIT();

        const uint32_t st = sb + (kt % NSTG) * STG_B;
#pragma unroll
        for (int ks = 0; ks < 2; ks++) {   // 2 x k32 per stage
            const uint32_t aCk = ((uint32_t)(ks * 2) + aC0) ^ aSw;
            const uint32_t bCk = ((uint32_t)(ks * 2) + bC0) ^ bSw;
            const uint32_t aAddr = st + aRow * ROW_B + aCk * 16;
            const uint32_t bAddr = st + 2 * A_B + bRow * ROW_B + bCk * 16;
            uint32_t a1f[4][4], a0f[4][4], b1f[2][4], b0f[2][4];
#pragma unroll
            for (int mi = 0; mi < 4; mi++) {
                ldm4(a1f[mi], aAddr + mi * 16 * ROW_B);
                ldm4(a0f[mi], aAddr + A_B + mi * 16 * ROW_B);
            }
#pragma unroll
            for (int nb = 0; nb < 2; nb++) {
                ldm4(b1f[nb], bAddr + nb * 16 * ROW_B);
                ldm4(b0f[nb], bAddr + B_B + nb * 16 * ROW_B);
            }
#pragma unroll
            for (int mi = 0; mi < 4; mi++)
#pragma unroll
                for (int ni = 0; ni < 4; ni++) {
                    const uint32_t* b1p = &b1f[ni >> 1][(ni & 1) * 2];
                    const uint32_t* b0p = &b0f[ni >> 1][(ni & 1) * 2];
                    mma_s8(acc1[mi][ni], a1f[mi], b1p);   // hi*hi
                    mma_s8(acc2[mi][ni], a1f[mi], b0p);   // hi*lo
                    mma_s8(acc2[mi][ni], a0f[mi], b1p);   // lo*hi
                }
        }
    }

    // ---- epilogue: apply row/col scales, write fp32 ----
    const int qr = lane >> 2, qc = (lane & 3) * 2;
    const float* sAp = sA + z * sAz;
    const float* sBp = sB + z * sBz;
    float sav[4][2], sbv[4][2];
#pragma unroll
    for (int mi = 0; mi < 4; mi++) {
        const int m = bm + wm * 64 + mi * 16 + qr;
        sav[mi][0] = sAp[m]; sav[mi][1] = sAp[m + 8];
    }
#pragma unroll
    for (int ni = 0; ni < 4; ni++) {
        const int n = bn + wn * 32 + ni * 8 + qc;
        sbv[ni][0] = sBp[n]; sbv[ni][1] = sBp[n + 1];
    }
    float* Cw;
    long zoff = 0;
    if (FUSED) { Cw = (z == 0) ? C0 : (z == 1) ? C1 : C2; }
    else       { Cw = C0; zoff = (long)z * sC; }

#pragma unroll
    for (int mi = 0; mi < 4; mi++)
#pragma unroll
        for (int ni = 0; ni < 4; ni++) {
            const int m = bm + wm * 64 + mi * 16 + qr;
            const int n = bn + wn * 32 + ni * 8 + qc;
            float f0 = 16384.0f * (float)acc1[mi][ni][0] + 128.0f * (float)acc2[mi][ni][0];
            float f1 = 16384.0f * (float)acc1[mi][ni][1] + 128.0f * (float)acc2[mi][ni][1];
            float f2 = 16384.0f * (float)acc1[mi][ni][2] + 128.0f * (float)acc2[mi][ni][2];
            float f3 = 16384.0f * (float)acc1[mi][ni][3] + 128.0f * (float)acc2[mi][ni][3];
            const long o0 = zoff + (long)m * N + n;
            const long o1 = o0 + 8L * N;
            *(float2*)(Cw + o0) = make_float2(sav[mi][0] * sbv[ni][0] * f0,
                                              sav[mi][0] * sbv[ni][1] * f1);
            *(float2*)(Cw + o1) = make_float2(sav[mi][1] * sbv[ni][0] * f2,
                                              sav[mi][1] * sbv[ni][1] * f3);
        }
}

// ========================= reductions / quant ===============================
__device__ __forceinline__ float warpMax(float v) {
#pragma unroll
    for (int o = 16; o; o >>= 1) v = fmaxf(v, __shfl_xor_sync(0xFFFFFFFFu, v, o));
    return v;
}
__device__ __forceinline__ float warpSum(float v) {
#pragma unroll
    for (int o = 16; o; o >>= 1) v += __shfl_xor_sync(0xFFFFFFFFu, v, o);
    return v;
}

// per-row quantization: fp32 [rows, K] -> int8 digits + scale[row]
__global__ void rowquant(const float* __restrict__ in, int8_t* __restrict__ q1,
                         int8_t* __restrict__ q0, float* __restrict__ sc, int K)
{
    __shared__ float red[8];
    const long row = blockIdx.x;
    const float4* p = (const float4*)(in + row * (long)K);
    const int tid = threadIdx.x;
    const int n4 = K >> 2;

    float mx = 0.0f;
    for (int i = tid; i < n4; i += 256) {
        float4 f = p[i];
        mx = fmaxf(mx, fmaxf(fmaxf(fabsf(f.x), fabsf(f.y)), fmaxf(fabsf(f.z), fabsf(f.w))));
    }
    mx = warpMax(mx);
    if ((tid & 31) == 0) red[tid >> 5] = mx;
    __syncthreads();
    if (tid < 32) {
        float m = (tid < 8) ? red[tid] : 0.0f;
        m = warpMax(m);
        if (tid == 0) red[0] = m;
    }
    __syncthreads();
    mx = red[0];
    const float inv = (mx > 0.0f) ? 16256.0f / mx : 0.0f;
    if (tid == 0) sc[row] = (mx > 0.0f) ? mx / 16256.0f : 0.0f;

    char4* c1 = (char4*)(q1 + row * (long)K);
    char4* c0 = (char4*)(q0 + row * (long)K);
    for (int i = tid; i < n4; i += 256) {
        float4 f = p[i];
        int h0, l0, h1, l1, h2, l2, h3, l3;
        quant1(f.x, inv, h0, l0); quant1(f.y, inv, h1, l1);
        quant1(f.z, inv, h2, l2); quant1(f.w, inv, h3, l3);
        c1[i] = make_char4((char)h0, (char)h1, (char)h2, (char)h3);
        c0[i] = make_char4((char)l0, (char)l1, (char)l2, (char)l3);
    }
}

// column |max|/16256 of W matrices (per output channel)
__global__ void colmaxW(const float* __restrict__ w0, const float* __restrict__ w1,
                        const float* __restrict__ w2, float* __restrict__ sc)
{
    const int z = blockIdx.y;
    const float* ip = (z == 0) ? w0 : (z == 1) ? w1 : w2;
    const int col = blockIdx.x * 256 + threadIdx.x;
    float mx = 0.0f;
#pragma unroll 4
    for (int r = 0; r < D_DIM; r++)
        mx = fmaxf(mx, fabsf(ip[(long)r * D_DIM + col]));
    sc[z * D_DIM + col] = mx / 16256.0f;
}

// column |max|/16256 of V per batch
__global__ void colmaxV(const float* __restrict__ v, float* __restrict__ sc)
{
    const int z = blockIdx.y;
    const float* ip = v + (long)z * S_LEN * D_DIM;
    const int col = blockIdx.x * 256 + threadIdx.x;
    float mx = 0.0f;
#pragma unroll 4
    for (int r = 0; r < S_LEN; r++)
        mx = fmaxf(mx, fabsf(ip[(long)r * D_DIM + col]));
    sc[z * D_DIM + col] = mx / 16256.0f;
}

// transpose + quantize W -> W^T digits (scale per output row, from colmaxW)
__global__ void tquantW(const float* __restrict__ w0, const float* __restrict__ w1,
                        const float* __restrict__ w2, const float* __restrict__ csc,
                        int8_t* __restrict__ o1, int8_t* __restrict__ o0)
{
    __shared__ float t[32][33];
    const int z = blockIdx.z;
    const float* ip = (z == 0) ? w0 : (z == 1) ? w1 : w2;
    const long zo = (long)z * D_DIM * D_DIM;
    const int bx = blockIdx.x * 32, by = blockIdx.y * 32;
    const int tx = threadIdx.x;
#pragma unroll
    for (int i = threadIdx.y; i < 32; i += 8)
        t[i][tx] = ip[(long)(by + i) * D_DIM + bx + tx];
    __syncthreads();
#pragma unroll
    for (int i = threadIdx.y; i < 32; i += 8) {
        const float s = csc[z * D_DIM + bx + i];
        const float inv = (s > 0.0f) ? 1.0f / s : 0.0f;
        int a1, a0;
        quant1(t[tx][i], inv, a1, a0);
        const long o = zo + (long)(bx + i) * D_DIM + by + tx;
        o1[o] = (int8_t)a1;
        o0[o] = (int8_t)a0;
    }
}

// transpose + quantize V -> V^T digits per batch
__global__ void tquantV(const float* __restrict__ v, const float* __restrict__ csc,
                        int8_t* __restrict__ o1, int8_t* __restrict__ o0)
{
    __shared__ float t[32][33];
    const int z = blockIdx.z;
    const float* ip = v + (long)z * S_LEN * D_DIM;
    int8_t* p1 = o1 + (long)z * S_LEN * D_DIM;
    int8_t* p0 = o0 + (long)z * S_LEN * D_DIM;
    const int bx = blockIdx.x * 32, by = blockIdx.y * 32;
    const int tx = threadIdx.x;
#pragma unroll
    for (int i = threadIdx.y; i < 32; i += 8)
        t[i][tx] = ip[(long)(by + i) * D_DIM + bx + tx];
    __syncthreads();
#pragma unroll
    for (int i = threadIdx.y; i < 32; i += 8) {
        const float s = csc[z * D_DIM + bx + i];
        const float inv = (s > 0.0f) ? 1.0f / s : 0.0f;
        int a1, a0;
        quant1(t[tx][i], inv, a1, a0);
        const long o = (long)(bx + i) * S_LEN + by + tx;
        p1[o] = (int8_t)a1;
        p0[o] = (int8_t)a0;
    }
}

// softmax over score rows; emits quantized weights + scale (= inv/16256, exact)
__global__ void softmax_q(const float* __restrict__ Sc, int8_t* __restrict__ W1,
                          int8_t* __restrict__ W0, float* __restrict__ sw)
{
    __shared__ float red[8];
    const long row = blockIdx.x;
    const float4* p4 = (const float4*)(Sc + row * (long)S_LEN);
    const int tid = threadIdx.x;
    const float scale = 0.03125f;  // 1/sqrt(1024)

    float4 va = p4[tid], vb = p4[tid + 256];
    float v[8] = {va.x, va.y, va.z, va.w, vb.x, vb.y, vb.z, vb.w};
    float mx = -3.402823e38f;
#pragma unroll
    for (int i = 0; i < 8; i++) { v[i] *= scale; mx = fmaxf(mx, v[i]); }
    mx = warpMax(mx);
    if ((tid & 31) == 0) red[tid >> 5] = mx;
    __syncthreads();
    if (tid < 32) {
        float m = (tid < 8) ? red[tid] : -3.402823e38f;
        m = warpMax(m);
        if (tid == 0) red[0] = m;
    }
    __syncthreads();
    mx = red[0];
    __syncthreads();

    float s = 0.0f;
#pragma unroll
    for (int i = 0; i < 8; i++) { v[i] = __expf(v[i] - mx); s += v[i]; }
    s = warpSum(s);
    if ((tid & 31) == 0) red[tid >> 5] = s;
    __syncthreads();
    if (tid < 32) {
        float t = (tid < 8) ? red[tid] : 0.0f;
        t = warpSum(t);
        if (tid == 0) red[0] = t;
    }
    __syncthreads();
    const float inv = 1.0f / red[0];
    if (tid == 0) sw[row] = inv * (1.0f / 16256.0f);

    // q = exp(v-mx)*16256 in [0, 16256]; weight = (inv/16256) * q
    char4 h[2], l[2];
#pragma unroll
    for (int g = 0; g < 2; g++) {
        int a1[4], a0[4];
#pragma unroll
        for (int j = 0; j < 4; j++) {
            float q = rintf(v[g * 4 + j] * 16256.0f);
            a1[j] = (int)rintf(q * 0.0078125f);
            a0[j] = (int)q - (a1[j] << 7);
        }
        h[g] = make_char4((char)a1[0], (char)a1[1], (char)a1[2], (char)a1[3]);
        l[g] = make_char4((char)a0[0], (char)a0[1], (char)a0[2], (char)a0[3]);
    }
    char4* w1 = (char4*)(W1 + row * (long)S_LEN);
    char4* w0 = (char4*)(W0 + row * (long)S_LEN);
    w1[tid] = h[0]; w1[tid + 256] = h[1];
    w0[tid] = l[0]; w0[tid + 256] = l[1];
}

// ============================ host side =====================================
extern "C" void kernel_launch(void* const* d_in, const int* in_sizes, int n_in,
                              void* d_out, int out_size)
{
    const float* x  = (const float*)d_in[0];
    const float* Wq = (const float*)d_in[1];
    const float* Wk = (const float*)d_in[2];
    const float* Wv = (const float*)d_in[3];
    float* out = (float*)d_out;

    void *xq1, *xq0, *wq1, *wq0, *qf, *kf, *vf, *qq1, *qq0, *kq1, *kq0;
    void *vt1, *vt0, *sc, *sw1, *sw0;
    void *sx, *swsc, *sq, *sk, *svt, *ssw;
    cudaGetSymbolAddress(&xq1, g_xq1); cudaGetSymbolAddress(&xq0, g_xq0);
    cudaGetSymbolAddress(&wq1, g_wq1); cudaGetSymbolAddress(&wq0, g_wq0);
    cudaGetSymbolAddress(&qf, g_qf);   cudaGetSymbolAddress(&kf, g_kf);
    cudaGetSymbolAddress(&vf, g_vf);
    cudaGetSymbolAddress(&qq1, g_qq1); cudaGetSymbolAddress(&qq0, g_qq0);
    cudaGetSymbolAddress(&kq1, g_kq1); cudaGetSymbolAddress(&kq0, g_kq0);
    cudaGetSymbolAddress(&vt1, g_vt1); cudaGetSymbolAddress(&vt0, g_vt0);
    cudaGetSymbolAddress(&sc, g_sc);
    cudaGetSymbolAddress(&sw1, g_sw1); cudaGetSymbolAddress(&sw0, g_sw0);
    cudaGetSymbolAddress(&sx, g_sx);   cudaGetSymbolAddress(&swsc, g_swsc);
    cudaGetSymbolAddress(&sq, g_sq);   cudaGetSymbolAddress(&sk, g_sk);
    cudaGetSymbolAddress(&svt, g_svt); cudaGetSymbolAddress(&ssw, g_ssw);

    cudaFuncSetAttribute(gemm_i8<0>, cudaFuncAttributeMaxDynamicSharedMemorySize, SMEM_SZ);
    cudaFuncSetAttribute(gemm_i8<1>, cudaFuncAttributeMaxDynamicSharedMemorySize, SMEM_SZ);

    const long SD = (long)S_LEN * D_DIM, SS = (long)S_LEN * S_LEN;
    const long W1s = (long)D_DIM * D_DIM;
    dim3 tb(32, 8);

    // ---- quantize inputs ----
    rowquant<<<MTOT, 256>>>(x, (int8_t*)xq1, (int8_t*)xq0, (float*)sx, D_DIM);
    colmaxW<<<dim3(D_DIM / 256, 3), 256>>>(Wq, Wk, Wv, (float*)swsc);
    tquantW<<<dim3(32, 32, 3), tb>>>(Wq, Wk, Wv, (const float*)swsc,
                                     (int8_t*)wq1, (int8_t*)wq0);

    // ---- fused QKV projection (fp32 out) ----
    gemm_i8<1><<<dim3(D_DIM / 64, MTOT / 128, 3), 128, SMEM_SZ>>>(
        (int8_t*)xq1, (int8_t*)xq0, (int8_t*)wq1, (int8_t*)wq0,
        (const float*)sx, (const float*)swsc, 0, D_DIM,
        (float*)qf, (float*)kf, (float*)vf,
        D_DIM, D_DIM, 0, W1s, 0);

    // ---- quantize Q, K (row-wise) and V (transposed, column-wise) ----
    rowquant<<<MTOT, 256>>>((const float*)qf, (int8_t*)qq1, (int8_t*)qq0, (float*)sq, D_DIM);
    rowquant<<<MTOT, 256>>>((const float*)kf, (int8_t*)kq1, (int8_t*)kq0, (float*)sk, D_DIM);
    colmaxV<<<dim3(D_DIM / 256, BATCH), 256>>>((const float*)vf, (float*)svt);
    tquantV<<<dim3(D_DIM / 32, S_LEN / 32, BATCH), tb>>>(
        (const float*)vf, (const float*)svt, (int8_t*)vt1, (int8_t*)vt0);

    // ---- scores = Q K^T per batch (fp32 out) ----
    gemm_i8<0><<<dim3(S_LEN / 64, S_LEN / 128, BATCH), 128, SMEM_SZ>>>(
        (int8_t*)qq1, (int8_t*)qq0, (int8_t*)kq1, (int8_t*)kq0,
        (const float*)sq, (const float*)sk, S_LEN, S_LEN,
        (float*)sc, nullptr, nullptr,
        S_LEN, D_DIM, SD, SD, SS);

    // ---- softmax (emits quantized weights + scale) ----
    softmax_q<<<MTOT, 256>>>((const float*)sc, (int8_t*)sw1, (int8_t*)sw0, (float*)ssw);

    // ---- out = softmaxW * V ----
    gemm_i8<0><<<dim3(D_DIM / 64, S_LEN / 128, BATCH), 128, SMEM_SZ>>>(
        (int8_t*)sw1, (int8_t*)sw0, (int8_t*)vt1, (int8_t*)vt0,
        (const float*)ssw, (const float*)svt, S_LEN, D_DIM,
        out, nullptr, nullptr,
        D_DIM, S_LEN, SS, SD, SD);
}

// round 8
// speedup vs baseline: 3.1192x; 3.1192x over previous
#include <cuda_runtime.h>
#include <cuda_fp16.h>
#include <cstdint>

#define S_LEN 2048
#define D_DIM 1024
#define BATCH 4
#define MTOT  (BATCH * S_LEN)   // 8192

// ============================ device scratch ================================
__device__ __half g_xh [(size_t)MTOT * D_DIM];
__device__ __half g_xl [(size_t)MTOT * D_DIM];
__device__ __half g_wth[(size_t)3 * D_DIM * D_DIM];   // W^T hi (q,k,v) contiguous
__device__ __half g_wtl[(size_t)3 * D_DIM * D_DIM];
__device__ __half g_qh [(size_t)MTOT * D_DIM];
__device__ __half g_ql [(size_t)MTOT * D_DIM];
__device__ __half g_kh [(size_t)MTOT * D_DIM];
__device__ __half g_kl [(size_t)MTOT * D_DIM];
__device__ float  g_v  [(size_t)MTOT * D_DIM];
__device__ __half g_vth[(size_t)BATCH * D_DIM * S_LEN];  // V^T per batch
__device__ __half g_vtl[(size_t)BATCH * D_DIM * S_LEN];
__device__ float  g_sc [(size_t)BATCH * S_LEN * S_LEN];
__device__ __half g_wh [(size_t)BATCH * S_LEN * S_LEN];
__device__ __half g_wl [(size_t)BATCH * S_LEN * S_LEN];

// ============================ PTX helpers ===================================
__device__ __forceinline__ uint32_t smem_u32(const void* p) {
    uint32_t a;
    asm("{ .reg .u64 t; cvta.to.shared.u64 t, %1; cvt.u32.u64 %0, t; }" : "=r"(a) : "l"(p));
    return a;
}
__device__ __forceinline__ void cp16(uint32_t s, const void* g) {
    asm volatile("cp.async.cg.shared.global [%0], [%1], 16;" :: "r"(s), "l"(g) : "memory");
}
#define CP_COMMIT() asm volatile("cp.async.commit_group;" ::: "memory")
#define CP_WAIT(n)  asm volatile("cp.async.wait_group %0;" :: "n"(n) : "memory")

__device__ __forceinline__ void ldm4(uint32_t r[4], uint32_t a) {
    asm volatile("ldmatrix.sync.aligned.m8n8.x4.shared.b16 {%0,%1,%2,%3}, [%4];"
                 : "=r"(r[0]), "=r"(r[1]), "=r"(r[2]), "=r"(r[3]) : "r"(a));
}
// main term: fp16 inputs, f32 accumulate
__device__ __forceinline__ void mmaF(float c[4], const uint32_t a[4], const uint32_t b[2]) {
    asm volatile("mma.sync.aligned.m16n8k16.row.col.f32.f16.f16.f32 "
                 "{%0,%1,%2,%3}, {%4,%5,%6,%7}, {%8,%9}, {%0,%1,%2,%3};"
                 : "+f"(c[0]), "+f"(c[1]), "+f"(c[2]), "+f"(c[3])
                 : "r"(a[0]), "r"(a[1]), "r"(a[2]), "r"(a[3]), "r"(b[0]), "r"(b[1]));
}
// cross terms: fp16 inputs, f16 accumulate (half-register, potentially 2x rate)
__device__ __forceinline__ void mmaH(uint32_t c[2], const uint32_t a[4], const uint32_t b[2]) {
    asm volatile("mma.sync.aligned.m16n8k16.row.col.f16.f16.f16.f16 "
                 "{%0,%1}, {%2,%3,%4,%5}, {%6,%7}, {%0,%1};"
                 : "+r"(c[0]), "+r"(c[1])
                 : "r"(a[0]), "r"(a[1]), "r"(a[2]), "r"(a[3]), "r"(b[0]), "r"(b[1]));
}

__device__ __forceinline__ void hsplit(float f, __half& h, __half& l) {
    h = __float2half_rn(f);
    l = __float2half_rn(f - __half2float(h));
}

// ====================== split-fp16 HMMA GEMM ================================
// C[M,N] = (Ah+Al)[M,K] * (Bh+Bl)[N,K]^T   (K-major fp16 digits, 11+11 bits)
// hh -> f32 acc; (hl + lh) -> shared f16 acc (error ~2^-22 overall).
// CTA 128x128x32, 128 threads, 4 warps of 64x64, 2 CTAs/SM.
// XOR chunk swizzle on 64B rows: phys_chunk = c ^ ((row>>1)&3).
constexpr int ROW_B  = 64;
constexpr int COMP_B = 128 * ROW_B;   // 8192 B per component tile
constexpr int STG_B  = 4 * COMP_B;    // 32768 B (Ah,Al,Bh,Bl)
constexpr int NSTG   = 3;
constexpr int SMEM_SZ = NSTG * STG_B; // 98304 B -> 2 CTAs/SM

__device__ __forceinline__ void load_stage(uint32_t base,
    const __half* __restrict__ ah, const __half* __restrict__ al,
    const __half* __restrict__ bh, const __half* __restrict__ bl,
    int bm, int bn, int kt, int K, int tid)
{
    const int r  = tid >> 2;
    const int c  = tid & 3;
    const int kc = kt * 32 + c * 8;
    const int cp = c ^ ((r >> 1) & 3);
#pragma unroll
    for (int g = 0; g < 4; g++) {
        const int row = r + g * 32;
        const uint32_t so = (uint32_t)row * ROW_B + cp * 16;
        const long ga = (long)(bm + row) * K + kc;
        const long gb = (long)(bn + row) * K + kc;
        cp16(base + so,              ah + ga);
        cp16(base + COMP_B + so,     al + ga);
        cp16(base + 2 * COMP_B + so, bh + gb);
        cp16(base + 3 * COMP_B + so, bl + gb);
    }
}

// EPI=0: fp32 C (z-batched). EPI=2: fused QKV: z0->split(Ch,Cl), z1->split(Ch2,Cl2), z2->fp32 C.
template <int EPI>
__global__ void __launch_bounds__(128, 2)
gemm_mma(const __half* __restrict__ Agh, const __half* __restrict__ Agl,
         const __half* __restrict__ Bgh, const __half* __restrict__ Bgl,
         float* __restrict__ C, __half* __restrict__ Ch, __half* __restrict__ Cl,
         __half* __restrict__ Ch2, __half* __restrict__ Cl2,
         int N, int K, long sA, long sB, long sC)
{
    extern __shared__ __align__(128) char smem[];
    const uint32_t sb = smem_u32(smem);
    const int tid = threadIdx.x, lane = tid & 31, warp = tid >> 5;
    const int wm = warp >> 1, wn = warp & 1;
    const int bm = blockIdx.y * 128, bn = blockIdx.x * 128, z = blockIdx.z;

    const __half* Ah = Agh + (long)z * sA;
    const __half* Al = Agl + (long)z * sA;
    const __half* Bh = Bgh + (long)z * sB;
    const __half* Bl = Bgl + (long)z * sB;

    const int nk = K >> 5;

    const uint32_t aRow = (uint32_t)(wm * 64 + (lane & 15));
    const uint32_t aSw  = (aRow >> 1) & 3;
    const uint32_t aC0  = (uint32_t)((lane >> 4) & 1);
    const uint32_t bRow0 = (uint32_t)((lane & 7) | (((lane >> 4) & 1) << 3));
    const uint32_t bRow = (uint32_t)(wn * 64) + bRow0;
    const uint32_t bSw  = (bRow0 >> 1) & 3;
    const uint32_t bC0  = (uint32_t)((lane >> 3) & 1);

    float    accF[4][8][4];
    uint32_t accH[4][8][2];
#pragma unroll
    for (int i = 0; i < 4; i++)
#pragma unroll
        for (int j = 0; j < 8; j++) {
#pragma unroll
            for (int q = 0; q < 4; q++) accF[i][j][q] = 0.0f;
            accH[i][j][0] = 0u; accH[i][j][1] = 0u;
        }

#pragma unroll
    for (int s = 0; s < NSTG - 1; s++) {
        load_stage(sb + s * STG_B, Ah, Al, Bh, Bl, bm, bn, s, K, tid);
        CP_COMMIT();
    }

    for (int kt = 0; kt < nk; kt++) {
        CP_WAIT(NSTG - 2);
        __syncthreads();

        const int nx = kt + NSTG - 1;
        if (nx < nk)
            load_stage(sb + (nx % NSTG) * STG_B, Ah, Al, Bh, Bl, bm, bn, nx, K, tid);
        CP_COMMIT();

        const uint32_t st = sb + (kt % NSTG) * STG_B;
#pragma unroll
        for (int k16 = 0; k16 < 2; k16++) {
            const uint32_t aCk = ((uint32_t)(k16 * 2) + aC0) ^ aSw;
            const uint32_t bCk = ((uint32_t)(k16 * 2) + bC0) ^ bSw;
            const uint32_t aAddr = st + aRow * ROW_B + aCk * 16;
            const uint32_t bAddr = st + 2 * COMP_B + bRow * ROW_B + bCk * 16;
            uint32_t ah[4][4], al[4][4];
#pragma unroll
            for (int mi = 0; mi < 4; mi++) {
                ldm4(ah[mi], aAddr + mi * 16 * ROW_B);
                ldm4(al[mi], aAddr + COMP_B + mi * 16 * ROW_B);
            }
            // stream B fragments (keeps live regs ~252 <= 256)
#pragma unroll
            for (int nb = 0; nb < 4; nb++) {
                uint32_t bh[4], bl[4];
                ldm4(bh, bAddr + nb * 16 * ROW_B);
                ldm4(bl, bAddr + COMP_B + nb * 16 * ROW_B);
#pragma unroll
                for (int mi = 0; mi < 4; mi++)
#pragma unroll
                    for (int h = 0; h < 2; h++) {
                        const int ni = nb * 2 + h;
                        mmaF(accF[mi][ni], ah[mi], &bh[h * 2]);   // hi*hi -> f32
                        mmaH(accH[mi][ni], ah[mi], &bl[h * 2]);   // hi*lo -> f16
                        mmaH(accH[mi][ni], al[mi], &bh[h * 2]);   // lo*hi -> f16
                    }
            }
        }
    }

    // ---- epilogue: C = hh + cross ----
    bool wantF;
    long zoff;
    __half* outH = Ch;
    __half* outL = Cl;
    if (EPI == 0) { wantF = true; zoff = (long)z * sC; }
    else {
        zoff = 0;
        wantF = (z == 2);
        if (z == 1) { outH = Ch2; outL = Cl2; }
    }

    const int qr = lane >> 2, qc = (lane & 3) * 2;
#pragma unroll
    for (int mi = 0; mi < 4; mi++)
#pragma unroll
        for (int ni = 0; ni < 8; ni++) {
            const int m = bm + wm * 64 + mi * 16 + qr;
            const int n = bn + wn * 64 + ni * 8 + qc;
            const long o0 = zoff + (long)m * N + n;
            const long o1 = o0 + 8L * N;
            float2 x01 = __half22float2(*(const __half2*)&accH[mi][ni][0]);
            float2 x23 = __half22float2(*(const __half2*)&accH[mi][ni][1]);
            float f0 = accF[mi][ni][0] + x01.x;
            float f1 = accF[mi][ni][1] + x01.y;
            float f2 = accF[mi][ni][2] + x23.x;
            float f3 = accF[mi][ni][3] + x23.y;
            if (wantF) {
                *(float2*)(C + o0) = make_float2(f0, f1);
                *(float2*)(C + o1) = make_float2(f2, f3);
            } else {
                __half h0, l0, h1, l1, h2, l2, h3, l3;
                hsplit(f0, h0, l0); hsplit(f1, h1, l1);
                hsplit(f2, h2, l2); hsplit(f3, h3, l3);
                *(__half2*)(outH + o0) = __halves2half2(h0, h1);
                *(__half2*)(outH + o1) = __halves2half2(h2, h3);
                *(__half2*)(outL + o0) = __halves2half2(l0, l1);
                *(__half2*)(outL + o1) = __halves2half2(l2, l3);
            }
        }
}

// =========================== prep kernels ===================================
__global__ void split_f32(const float* __restrict__ in, __half* __restrict__ oh,
                          __half* __restrict__ ol)
{
    long i = ((long)blockIdx.x * 256 + threadIdx.x) * 4;
    float4 f = *(const float4*)(in + i);
    __half h0, l0, h1, l1, h2, l2, h3, l3;
    hsplit(f.x, h0, l0); hsplit(f.y, h1, l1);
    hsplit(f.z, h2, l2); hsplit(f.w, h3, l3);
    __half2* hp = (__half2*)(oh + i);
    __half2* lp = (__half2*)(ol + i);
    hp[0] = __halves2half2(h0, h1); hp[1] = __halves2half2(h2, h3);
    lp[0] = __halves2half2(l0, l1); lp[1] = __halves2half2(l2, l3);
}

// transpose [R,C] -> [C,R] with hi/lo fp16 split; z batches via strides
__global__ void tsplit(const float* __restrict__ in, __half* __restrict__ oh,
                       __half* __restrict__ ol, int R, int C, long sIn, long sOut)
{
    __shared__ float t[32][33];
    const int bx = blockIdx.x * 32, by = blockIdx.y * 32;
    const float* ip = in + (long)blockIdx.z * sIn;
    __half* ohp = oh + (long)blockIdx.z * sOut;
    __half* olp = ol + (long)blockIdx.z * sOut;
    const int tx = threadIdx.x;
#pragma unroll
    for (int i = threadIdx.y; i < 32; i += 8)
        t[i][tx] = ip[(long)(by + i) * C + bx + tx];
    __syncthreads();
#pragma unroll
    for (int i = threadIdx.y; i < 32; i += 8) {
        __half h, l;
        hsplit(t[tx][i], h, l);
        long o = (long)(bx + i) * R + by + tx;
        ohp[o] = h;
        olp[o] = l;
    }
}

// fused weight transpose+split: z selects Wq/Wk/Wv, output at z*D*D
__global__ void tsplitW(const float* __restrict__ w0, const float* __restrict__ w1,
                        const float* __restrict__ w2,
                        __half* __restrict__ oh, __half* __restrict__ ol)
{
    __shared__ float t[32][33];
    const int z = blockIdx.z;
    const float* ip = (z == 0) ? w0 : (z == 1) ? w1 : w2;
    const long zo = (long)z * D_DIM * D_DIM;
    const int bx = blockIdx.x * 32, by = blockIdx.y * 32;
    const int tx = threadIdx.x;
#pragma unroll
    for (int i = threadIdx.y; i < 32; i += 8)
        t[i][tx] = ip[(long)(by + i) * D_DIM + bx + tx];
    __syncthreads();
#pragma unroll
    for (int i = threadIdx.y; i < 32; i += 8) {
        __half h, l;
        hsplit(t[tx][i], h, l);
        long o = zo + (long)(bx + i) * D_DIM + by + tx;
        oh[o] = h;
        ol[o] = l;
    }
}

// ============================ softmax =======================================
__device__ __forceinline__ float warpMax(float v) {
#pragma unroll
    for (int o = 16; o; o >>= 1) v = fmaxf(v, __shfl_xor_sync(0xFFFFFFFFu, v, o));
    return v;
}
__device__ __forceinline__ float warpSum(float v) {
#pragma unroll
    for (int o = 16; o; o >>= 1) v += __shfl_xor_sync(0xFFFFFFFFu, v, o);
    return v;
}

struct alignas(8) h4 { __half2 a, b; };

__global__ void softmax_rows(const float* __restrict__ Sc,
                             __half* __restrict__ Wh, __half* __restrict__ Wl)
{
    __shared__ float red[8];
    const long row = blockIdx.x;
    const float4* p4 = (const float4*)(Sc + row * (long)S_LEN);
    const int tid = threadIdx.x;
    const float scale = 0.03125f;  // 1/sqrt(1024)

    float4 va = p4[tid], vb = p4[tid + 256];
    float v[8] = {va.x, va.y, va.z, va.w, vb.x, vb.y, vb.z, vb.w};
    float mx = -3.402823e38f;
#pragma unroll
    for (int i = 0; i < 8; i++) { v[i] *= scale; mx = fmaxf(mx, v[i]); }
    mx = warpMax(mx);
    if ((tid & 31) == 0) red[tid >> 5] = mx;
    __syncthreads();
    if (tid < 32) {
        float m = (tid < 8) ? red[tid] : -3.402823e38f;
        m = warpMax(m);
        if (tid == 0) red[0] = m;
    }
    __syncthreads();
    mx = red[0];
    __syncthreads();

    float s = 0.0f;
#pragma unroll
    for (int i = 0; i < 8; i++) { v[i] = __expf(v[i] - mx); s += v[i]; }
    s = warpSum(s);
    if ((tid & 31) == 0) red[tid >> 5] = s;
    __syncthreads();
    if (tid < 32) {
        float t = (tid < 8) ? red[tid] : 0.0f;
        t = warpSum(t);
        if (tid == 0) red[0] = t;
    }
    __syncthreads();
    const float inv = 1.0f / red[0];

    __half h[8], l[8];
#pragma unroll
    for (int i = 0; i < 8; i++) hsplit(v[i] * inv, h[i], l[i]);
    h4* wh4 = (h4*)(Wh + row * (long)S_LEN);
    h4* wl4 = (h4*)(Wl + row * (long)S_LEN);
    wh4[tid]       = {__halves2half2(h[0], h[1]), __halves2half2(h[2], h[3])};
    wh4[tid + 256] = {__halves2half2(h[4], h[5]), __halves2half2(h[6], h[7])};
    wl4[tid]       = {__halves2half2(l[0], l[1]), __halves2half2(l[2], l[3])};
    wl4[tid + 256] = {__halves2half2(l[4], l[5]), __halves2half2(l[6], l[7])};
}

// ============================ host side =====================================
extern "C" void kernel_launch(void* const* d_in, const int* in_sizes, int n_in,
                              void* d_out, int out_size)
{
    const float* x  = (const float*)d_in[0];
    const float* Wq = (const float*)d_in[1];
    const float* Wk = (const float*)d_in[2];
    const float* Wv = (const float*)d_in[3];
    float* out = (float*)d_out;

    void *xh, *xl, *wth, *wtl, *qh, *ql, *kh, *kl, *v, *vth, *vtl, *sc, *wh, *wl;
    cudaGetSymbolAddress(&xh, g_xh);   cudaGetSymbolAddress(&xl, g_xl);
    cudaGetSymbolAddress(&wth, g_wth); cudaGetSymbolAddress(&wtl, g_wtl);
    cudaGetSymbolAddress(&qh, g_qh);   cudaGetSymbolAddress(&ql, g_ql);
    cudaGetSymbolAddress(&kh, g_kh);   cudaGetSymbolAddress(&kl, g_kl);
    cudaGetSymbolAddress(&v, g_v);
    cudaGetSymbolAddress(&vth, g_vth); cudaGetSymbolAddress(&vtl, g_vtl);
    cudaGetSymbolAddress(&sc, g_sc);
    cudaGetSymbolAddress(&wh, g_wh);   cudaGetSymbolAddress(&wl, g_wl);

    cudaFuncSetAttribute(gemm_mma<0>, cudaFuncAttributeMaxDynamicSharedMemorySize, SMEM_SZ);
    cudaFuncSetAttribute(gemm_mma<2>, cudaFuncAttributeMaxDynamicSharedMemorySize, SMEM_SZ);

    const long SD = (long)S_LEN * D_DIM, SS = (long)S_LEN * S_LEN;
    const long W1 = (long)D_DIM * D_DIM;
    dim3 tb(32, 8);

    // ---- data prep ----
    split_f32<<<(int)((long)MTOT * D_DIM / 1024), 256>>>(x, (__half*)xh, (__half*)xl);
    tsplitW<<<dim3(32, 32, 3), tb>>>(Wq, Wk, Wv, (__half*)wth, (__half*)wtl);

    // ---- fused QKV projection: z=0 -> Q split, z=1 -> K split, z=2 -> V fp32
    dim3 gp(D_DIM / 128, MTOT / 128, 3);
    gemm_mma<2><<<gp, 128, SMEM_SZ>>>((__half*)xh, (__half*)xl, (__half*)wth, (__half*)wtl,
        (float*)v, (__half*)qh, (__half*)ql, (__half*)kh, (__half*)kl,
        D_DIM, D_DIM, 0, W1, 0);

    // V -> V^T hi/lo per batch
    tsplit<<<dim3(D_DIM / 32, S_LEN / 32, BATCH), tb>>>(
        (const float*)v, (__half*)vth, (__half*)vtl, S_LEN, D_DIM, SD, SD);

    // scores = Q K^T per batch
    dim3 gs(S_LEN / 128, S_LEN / 128, BATCH);
    gemm_mma<0><<<gs, 128, SMEM_SZ>>>((__half*)qh, (__half*)ql, (__half*)kh, (__half*)kl,
        (float*)sc, nullptr, nullptr, nullptr, nullptr, S_LEN, D_DIM, SD, SD, SS);

    softmax_rows<<<BATCH * S_LEN, 256>>>((const float*)sc, (__half*)wh, (__half*)wl);

    // out = softmaxW * V  (B = V^T, K-major)
    dim3 ga(D_DIM / 128, S_LEN / 128, BATCH);
    gemm_mma<0><<<ga, 128, SMEM_SZ>>>((__half*)wh, (__half*)wl, (__half*)vth, (__half*)vtl,
        out, nullptr, nullptr, nullptr, nullptr, D_DIM, S_LEN, SS, SD, SD);
}

// round 9
// speedup vs baseline: 3.2824x; 1.0523x over previous
#include <cuda_runtime.h>
#include <cuda_bf16.h>
#include <cstdint>

#define S_LEN 2048
#define D_DIM 1024
#define BATCH 4
#define MTOT  (BATCH * S_LEN)   // 8192

typedef __nv_bfloat16 bf16;

// ============================ device scratch ================================
__device__ bf16  g_xh [(size_t)MTOT * D_DIM];
__device__ bf16  g_xl [(size_t)MTOT * D_DIM];
__device__ bf16  g_wth[(size_t)3 * D_DIM * D_DIM];   // W^T hi (q,k,v) contiguous
__device__ bf16  g_wtl[(size_t)3 * D_DIM * D_DIM];
__device__ bf16  g_qh [(size_t)MTOT * D_DIM];
__device__ bf16  g_ql [(size_t)MTOT * D_DIM];
__device__ bf16  g_kh [(size_t)MTOT * D_DIM];
__device__ bf16  g_kl [(size_t)MTOT * D_DIM];
__device__ float g_v  [(size_t)MTOT * D_DIM];
__device__ bf16  g_vth[(size_t)BATCH * D_DIM * S_LEN];  // V^T per batch
__device__ bf16  g_vtl[(size_t)BATCH * D_DIM * S_LEN];
__device__ float g_sc [(size_t)BATCH * S_LEN * S_LEN];
__device__ bf16  g_wh [(size_t)BATCH * S_LEN * S_LEN];
__device__ bf16  g_wl [(size_t)BATCH * S_LEN * S_LEN];

// ============================ PTX helpers ===================================
__device__ __forceinline__ uint32_t smem_u32(const void* p) {
    uint32_t a;
    asm("{ .reg .u64 t; cvta.to.shared.u64 t, %1; cvt.u32.u64 %0, t; }" : "=r"(a) : "l"(p));
    return a;
}
__device__ __forceinline__ void cp16(uint32_t s, const void* g) {
    asm volatile("cp.async.cg.shared.global [%0], [%1], 16;" :: "r"(s), "l"(g) : "memory");
}
#define CP_COMMIT() asm volatile("cp.async.commit_group;" ::: "memory")
#define CP_WAIT(n)  asm volatile("cp.async.wait_group %0;" :: "n"(n) : "memory")

__device__ __forceinline__ void ldm4(uint32_t r[4], uint32_t a) {
    asm volatile("ldmatrix.sync.aligned.m8n8.x4.shared.b16 {%0,%1,%2,%3}, [%4];"
                 : "=r"(r[0]), "=r"(r[1]), "=r"(r[2]), "=r"(r[3]) : "r"(a));
}
__device__ __forceinline__ void mma16816(float c[4], const uint32_t a[4], const uint32_t b[2]) {
    asm volatile("mma.sync.aligned.m16n8k16.row.col.f32.bf16.bf16.f32 "
                 "{%0,%1,%2,%3}, {%4,%5,%6,%7}, {%8,%9}, {%0,%1,%2,%3};"
                 : "+f"(c[0]), "+f"(c[1]), "+f"(c[2]), "+f"(c[3])
                 : "r"(a[0]), "r"(a[1]), "r"(a[2]), "r"(a[3]), "r"(b[0]), "r"(b[1]));
}

// ====================== split-bf16 HMMA GEMM (persistent) ===================
// C[M,N] = (Ah+Al)[M,K] * (Bh+Bl)[N,K]^T   (all K-major bf16)
// CTA 128x128x32, 128 threads, 4 warps of 64x64, 2 CTAs/SM.
// XOR chunk swizzle on 64B rows: phys_chunk = c ^ ((row>>1)&3).
// Persistent: grid = 2*numSMs; each CTA loops over tile jobs (kills wave tails).
constexpr int ROW_B  = 64;
constexpr int COMP_B = 128 * ROW_B;   // 8192 B per component tile
constexpr int STG_B  = 4 * COMP_B;    // 32768 B (Ah,Al,Bh,Bl)
constexpr int NSTG   = 3;
constexpr int SMEM_SZ = NSTG * STG_B; // 98304 B -> 2 CTAs/SM

__device__ __forceinline__ void load_stage(uint32_t base,
    const bf16* __restrict__ ah, const bf16* __restrict__ al,
    const bf16* __restrict__ bh, const bf16* __restrict__ bl,
    int bm, int bn, int kt, int K, int tid)
{
    const int r  = tid >> 2;
    const int c  = tid & 3;
    const int kc = kt * 32 + c * 8;
    const int cp = c ^ ((r >> 1) & 3);
#pragma unroll
    for (int g = 0; g < 4; g++) {
        const int row = r + g * 32;
        const uint32_t so = (uint32_t)row * ROW_B + cp * 16;
        const long ga = (long)(bm + row) * K + kc;
        const long gb = (long)(bn + row) * K + kc;
        cp16(base + so,              ah + ga);
        cp16(base + COMP_B + so,     al + ga);
        cp16(base + 2 * COMP_B + so, bh + gb);
        cp16(base + 3 * COMP_B + so, bl + gb);
    }
}

// EPI=0: fp32 C, z-batched via sA/sB/sC.
// EPI=2: fused QKV projection — z=0 -> split(Ch,Cl), z=1 -> split(Ch2,Cl2), z=2 -> fp32 C.
template <int EPI>
__global__ void __launch_bounds__(128, 2)
gemm_mma(const bf16* __restrict__ Agh, const bf16* __restrict__ Agl,
         const bf16* __restrict__ Bgh, const bf16* __restrict__ Bgl,
         float* __restrict__ C, bf16* __restrict__ Ch, bf16* __restrict__ Cl,
         bf16* __restrict__ Ch2, bf16* __restrict__ Cl2,
         int N, int K, long sA, long sB, long sC,
         int gx, int gy, int gz)
{
    extern __shared__ __align__(128) char smem[];
    const uint32_t sb = smem_u32(smem);
    const int tid = threadIdx.x, lane = tid & 31, warp = tid >> 5;
    const int wm = warp >> 1, wn = warp & 1;
    const int nk = K >> 5;
    const int njobs = gx * gy * gz;

    // ldmatrix per-thread address components (swizzle term invariant to +16 rows)
    const uint32_t aRow = (uint32_t)(wm * 64 + (lane & 15));
    const uint32_t aSw  = (aRow >> 1) & 3;
    const uint32_t aC0  = (uint32_t)((lane >> 4) & 1);
    const uint32_t bRow0 = (uint32_t)((lane & 7) | (((lane >> 4) & 1) << 3));
    const uint32_t bRow = (uint32_t)(wn * 64) + bRow0;
    const uint32_t bSw  = (bRow0 >> 1) & 3;
    const uint32_t bC0  = (uint32_t)((lane >> 3) & 1);
    const int qr = lane >> 2, qc = (lane & 3) * 2;

    for (int job = blockIdx.x; job < njobs; job += gridDim.x) {
        const int z  = job / (gx * gy);
        const int r2 = job - z * gx * gy;
        const int bm = (r2 / gx) * 128;
        const int bn = (r2 % gx) * 128;

        const bf16* Ah = Agh + (long)z * sA;
        const bf16* Al = Agl + (long)z * sA;
        const bf16* Bh = Bgh + (long)z * sB;
        const bf16* Bl = Bgl + (long)z * sB;

        float acc[4][8][4];
#pragma unroll
        for (int i = 0; i < 4; i++)
#pragma unroll
            for (int j = 0; j < 8; j++)
#pragma unroll
                for (int q = 0; q < 4; q++) acc[i][j][q] = 0.0f;

        // prologue: fill NSTG-1 stages
#pragma unroll
        for (int s = 0; s < NSTG - 1; s++) {
            load_stage(sb + s * STG_B, Ah, Al, Bh, Bl, bm, bn, s, K, tid);
            CP_COMMIT();
        }

        for (int kt = 0; kt < nk; kt++) {
            CP_WAIT(NSTG - 2);
            __syncthreads();

            const int nx = kt + NSTG - 1;
            if (nx < nk)
                load_stage(sb + (nx % NSTG) * STG_B, Ah, Al, Bh, Bl, bm, bn, nx, K, tid);
            CP_COMMIT();

            const uint32_t st = sb + (kt % NSTG) * STG_B;
#pragma unroll
            for (int k16 = 0; k16 < 2; k16++) {
                const uint32_t aCk = ((uint32_t)(k16 * 2) + aC0) ^ aSw;
                const uint32_t bCk = ((uint32_t)(k16 * 2) + bC0) ^ bSw;
                const uint32_t aAddr = st + aRow * ROW_B + aCk * 16;
                const uint32_t bAddr = st + 2 * COMP_B + bRow * ROW_B + bCk * 16;
                uint32_t ah[4][4], al[4][4], bh[4][4], bl[4][4];
#pragma unroll
                for (int mi = 0; mi < 4; mi++) {
                    ldm4(ah[mi], aAddr + mi * 16 * ROW_B);
                    ldm4(al[mi], aAddr + COMP_B + mi * 16 * ROW_B);
                }
#pragma unroll
                for (int nb = 0; nb < 4; nb++) {
                    ldm4(bh[nb], bAddr + nb * 16 * ROW_B);
                    ldm4(bl[nb], bAddr + COMP_B + nb * 16 * ROW_B);
                }
#pragma unroll
                for (int mi = 0; mi < 4; mi++)
#pragma unroll
                    for (int ni = 0; ni < 8; ni++) {
                        const uint32_t* bhp = &bh[ni >> 1][(ni & 1) * 2];
                        const uint32_t* blp = &bl[ni >> 1][(ni & 1) * 2];
                        mma16816(acc[mi][ni], ah[mi], bhp);  // hi*hi
                        mma16816(acc[mi][ni], ah[mi], blp);  // hi*lo
                        mma16816(acc[mi][ni], al[mi], bhp);  // lo*hi
                    }
            }
        }
        // protect the final compute stage from the next job's prologue writes
        __syncthreads();

        // ---- epilogue ----
        bool wantF;
        long zoff;
        bf16* outH = Ch;
        bf16* outL = Cl;
        if (EPI == 0) { wantF = true; zoff = (long)z * sC; }
        else {
            zoff = 0;
            wantF = (z == 2);
            if (z == 1) { outH = Ch2; outL = Cl2; }
        }

#pragma unroll
        for (int mi = 0; mi < 4; mi++)
#pragma unroll
            for (int ni = 0; ni < 8; ni++) {
                const int m = bm + wm * 64 + mi * 16 + qr;
                const int n = bn + wn * 64 + ni * 8 + qc;
                const long o0 = zoff + (long)m * N + n;
                const long o1 = o0 + 8L * N;
                if (wantF) {
                    *(float2*)(C + o0) = make_float2(acc[mi][ni][0], acc[mi][ni][1]);
                    *(float2*)(C + o1) = make_float2(acc[mi][ni][2], acc[mi][ni][3]);
                } else {
                    float x0 = acc[mi][ni][0], y0 = acc[mi][ni][1];
                    float x1 = acc[mi][ni][2], y1 = acc[mi][ni][3];
                    bf16 hx0 = __float2bfloat16(x0), hy0 = __float2bfloat16(y0);
                    bf16 hx1 = __float2bfloat16(x1), hy1 = __float2bfloat16(y1);
                    *(__nv_bfloat162*)(outH + o0) = __nv_bfloat162(hx0, hy0);
                    *(__nv_bfloat162*)(outH + o1) = __nv_bfloat162(hx1, hy1);
                    *(__nv_bfloat162*)(outL + o0) = __nv_bfloat162(
                        __float2bfloat16(x0 - __bfloat162float(hx0)),
                        __float2bfloat16(y0 - __bfloat162float(hy0)));
                    *(__nv_bfloat162*)(outL + o1) = __nv_bfloat162(
                        __float2bfloat16(x1 - __bfloat162float(hx1)),
                        __float2bfloat16(y1 - __bfloat162float(hy1)));
                }
            }
    }
}

// =========================== prep kernels ===================================
__global__ void split_f32(const float* __restrict__ in, bf16* __restrict__ oh,
                          bf16* __restrict__ ol)
{
    long i = ((long)blockIdx.x * 256 + threadIdx.x) * 4;
    float4 f = *(const float4*)(in + i);
    bf16 h0 = __float2bfloat16(f.x), h1 = __float2bfloat16(f.y);
    bf16 h2 = __float2bfloat16(f.z), h3 = __float2bfloat16(f.w);
    __nv_bfloat162* hp = (__nv_bfloat162*)(oh + i);
    __nv_bfloat162* lp = (__nv_bfloat162*)(ol + i);
    hp[0] = __nv_bfloat162(h0, h1);
    hp[1] = __nv_bfloat162(h2, h3);
    lp[0] = __nv_bfloat162(__float2bfloat16(f.x - __bfloat162float(h0)),
                           __float2bfloat16(f.y - __bfloat162float(h1)));
    lp[1] = __nv_bfloat162(__float2bfloat16(f.z - __bfloat162float(h2)),
                           __float2bfloat16(f.w - __bfloat162float(h3)));
}

// transpose [R,C] -> [C,R] with hi/lo bf16 split; z batches via strides
__global__ void tsplit(const float* __restrict__ in, bf16* __restrict__ oh,
                       bf16* __restrict__ ol, int R, int C, long sIn, long sOut)
{
    __shared__ float t[32][33];
    const int bx = blockIdx.x * 32, by = blockIdx.y * 32;
    const float* ip = in + (long)blockIdx.z * sIn;
    bf16* ohp = oh + (long)blockIdx.z * sOut;
    bf16* olp = ol + (long)blockIdx.z * sOut;
    const int tx = threadIdx.x;
#pragma unroll
    for (int i = threadIdx.y; i < 32; i += 8)
        t[i][tx] = ip[(long)(by + i) * C + bx + tx];
    __syncthreads();
#pragma unroll
    for (int i = threadIdx.y; i < 32; i += 8) {
        float f = t[tx][i];
        bf16 h = __float2bfloat16(f);
        long o = (long)(bx + i) * R + by + tx;
        ohp[o] = h;
        olp[o] = __float2bfloat16(f - __bfloat162float(h));
    }
}

// fused weight transpose+split: z selects Wq/Wk/Wv, output at z*D*D
__global__ void tsplitW(const float* __restrict__ w0, const float* __restrict__ w1,
                        const float* __restrict__ w2,
                        bf16* __restrict__ oh, bf16* __restrict__ ol)
{
    __shared__ float t[32][33];
    const int z = blockIdx.z;
    const float* ip = (z == 0) ? w0 : (z == 1) ? w1 : w2;
    const long zo = (long)z * D_DIM * D_DIM;
    const int bx = blockIdx.x * 32, by = blockIdx.y * 32;
    const int tx = threadIdx.x;
#pragma unroll
    for (int i = threadIdx.y; i < 32; i += 8)
        t[i][tx] = ip[(long)(by + i) * D_DIM + bx + tx];
    __syncthreads();
#pragma unroll
    for (int i = threadIdx.y; i < 32; i += 8) {
        float f = t[tx][i];
        bf16 h = __float2bfloat16(f);
        long o = zo + (long)(bx + i) * D_DIM + by + tx;
        oh[o] = h;
        ol[o] = __float2bfloat16(f - __bfloat162float(h));
    }
}

// ============================ softmax =======================================
__device__ __forceinline__ float warpMax(float v) {
#pragma unroll
    for (int o = 16; o; o >>= 1) v = fmaxf(v, __shfl_xor_sync(0xFFFFFFFFu, v, o));
    return v;
}
__device__ __forceinline__ float warpSum(float v) {
#pragma unroll
    for (int o = 16; o; o >>= 1) v += __shfl_xor_sync(0xFFFFFFFFu, v, o);
    return v;
}

struct alignas(8) bf16x4 { __nv_bfloat162 a, b; };

__global__ void softmax_rows(const float* __restrict__ Sc,
                             bf16* __restrict__ Wh, bf16* __restrict__ Wl)
{
    __shared__ float red[8];
    const long row = blockIdx.x;
    const float4* p4 = (const float4*)(Sc + row * (long)S_LEN);
    const int tid = threadIdx.x;
    const float scale = 0.03125f;  // 1/sqrt(1024)

    float4 va = p4[tid], vb = p4[tid + 256];
    float v[8] = {va.x, va.y, va.z, va.w, vb.x, vb.y, vb.z, vb.w};
    float mx = -3.402823e38f;
#pragma unroll
    for (int i = 0; i < 8; i++) { v[i] *= scale; mx = fmaxf(mx, v[i]); }
    mx = warpMax(mx);
    if ((tid & 31) == 0) red[tid >> 5] = mx;
    __syncthreads();
    if (tid < 32) {
        float m = (tid < 8) ? red[tid] : -3.402823e38f;
        m = warpMax(m);
        if (tid == 0) red[0] = m;
    }
    __syncthreads();
    mx = red[0];
    __syncthreads();

    float s = 0.0f;
#pragma unroll
    for (int i = 0; i < 8; i++) { v[i] = __expf(v[i] - mx); s += v[i]; }
    s = warpSum(s);
    if ((tid & 31) == 0) red[tid >> 5] = s;
    __syncthreads();
    if (tid < 32) {
        float t = (tid < 8) ? red[tid] : 0.0f;
        t = warpSum(t);
        if (tid == 0) red[0] = t;
    }
    __syncthreads();
    const float inv = 1.0f / red[0];

    bf16 h[8], l[8];
#pragma unroll
    for (int i = 0; i < 8; i++) {
        float w = v[i] * inv;
        h[i] = __float2bfloat16(w);
        l[i] = __float2bfloat16(w - __bfloat162float(h[i]));
    }
    bf16x4* wh4 = (bf16x4*)(Wh + row * (long)S_LEN);
    bf16x4* wl4 = (bf16x4*)(Wl + row * (long)S_LEN);
    wh4[tid]       = {__nv_bfloat162(h[0], h[1]), __nv_bfloat162(h[2], h[3])};
    wh4[tid + 256] = {__nv_bfloat162(h[4], h[5]), __nv_bfloat162(h[6], h[7])};
    wl4[tid]       = {__nv_bfloat162(l[0], l[1]), __nv_bfloat162(l[2], l[3])};
    wl4[tid + 256] = {__nv_bfloat162(l[4], l[5]), __nv_bfloat162(l[6], l[7])};
}

// ============================ host side =====================================
extern "C" void kernel_launch(void* const* d_in, const int* in_sizes, int n_in,
                              void* d_out, int out_size)
{
    const float* x  = (const float*)d_in[0];
    const float* Wq = (const float*)d_in[1];
    const float* Wk = (const float*)d_in[2];
    const float* Wv = (const float*)d_in[3];
    float* out = (float*)d_out;

    void *xh, *xl, *wth, *wtl, *qh, *ql, *kh, *kl, *v, *vth, *vtl, *sc, *wh, *wl;
    cudaGetSymbolAddress(&xh, g_xh);   cudaGetSymbolAddress(&xl, g_xl);
    cudaGetSymbolAddress(&wth, g_wth); cudaGetSymbolAddress(&wtl, g_wtl);
    cudaGetSymbolAddress(&qh, g_qh);   cudaGetSymbolAddress(&ql, g_ql);
    cudaGetSymbolAddress(&kh, g_kh);   cudaGetSymbolAddress(&kl, g_kl);
    cudaGetSymbolAddress(&v, g_v);
    cudaGetSymbolAddress(&vth, g_vth); cudaGetSymbolAddress(&vtl, g_vtl);
    cudaGetSymbolAddress(&sc, g_sc);
    cudaGetSymbolAddress(&wh, g_wh);   cudaGetSymbolAddress(&wl, g_wl);

    cudaFuncSetAttribute(gemm_mma<0>, cudaFuncAttributeMaxDynamicSharedMemorySize, SMEM_SZ);
    cudaFuncSetAttribute(gemm_mma<2>, cudaFuncAttributeMaxDynamicSharedMemorySize, SMEM_SZ);

    int nsm = 148;
    cudaDeviceGetAttribute(&nsm, cudaDevAttrMultiProcessorCount, 0);
    const int PGRID = 2 * nsm;   // persistent grid: 2 CTAs per SM

    const long SD = (long)S_LEN * D_DIM, SS = (long)S_LEN * S_LEN;
    const long W1 = (long)D_DIM * D_DIM;
    dim3 tb(32, 8);

    // ---- data prep ----
    split_f32<<<(int)((long)MTOT * D_DIM / 1024), 256>>>(x, (bf16*)xh, (bf16*)xl);
    tsplitW<<<dim3(32, 32, 3), tb>>>(Wq, Wk, Wv, (bf16*)wth, (bf16*)wtl);

    // ---- fused QKV projection (persistent): z=0 Q split, z=1 K split, z=2 V fp32
    {
        int gx = D_DIM / 128, gy = MTOT / 128, gz = 3;
        int grid = min(PGRID, gx * gy * gz);
        gemm_mma<2><<<grid, 128, SMEM_SZ>>>((bf16*)xh, (bf16*)xl, (bf16*)wth, (bf16*)wtl,
            (float*)v, (bf16*)qh, (bf16*)ql, (bf16*)kh, (bf16*)kl,
            D_DIM, D_DIM, 0, W1, 0, gx, gy, gz);
    }

    // V -> V^T hi/lo per batch
    tsplit<<<dim3(D_DIM / 32, S_LEN / 32, BATCH), tb>>>(
        (const float*)v, (bf16*)vth, (bf16*)vtl, S_LEN, D_DIM, SD, SD);

    // scores = Q K^T per batch (persistent)
    {
        int gx = S_LEN / 128, gy = S_LEN / 128, gz = BATCH;
        int grid = min(PGRID, gx * gy * gz);
        gemm_mma<0><<<grid, 128, SMEM_SZ>>>((bf16*)qh, (bf16*)ql, (bf16*)kh, (bf16*)kl,
            (float*)sc, nullptr, nullptr, nullptr, nullptr,
            S_LEN, D_DIM, SD, SD, SS, gx, gy, gz);
    }

    softmax_rows<<<BATCH * S_LEN, 256>>>((const float*)sc, (bf16*)wh, (bf16*)wl);

    // out = softmaxW * V  (B = V^T, K-major) (persistent)
    {
        int gx = D_DIM / 128, gy = S_LEN / 128, gz = BATCH;
        int grid = min(PGRID, gx * gy * gz);
        gemm_mma<0><<<grid, 128, SMEM_SZ>>>((bf16*)wh, (bf16*)wl, (bf16*)vth, (bf16*)vtl,
            out, nullptr, nullptr, nullptr, nullptr,
            D_DIM, S_LEN, SS, SD, SD, gx, gy, gz);
    }
}

// round 10
// speedup vs baseline: 3.7070x; 1.1294x over previous
#include <cuda_runtime.h>
#include <cuda_bf16.h>
#include <cstdint>

#define S_LEN 2048
#define D_DIM 1024
#define BATCH 4
#define MTOT  (BATCH * S_LEN)   // 8192

typedef __nv_bfloat16 bf16;

// ============================ device scratch ================================
__device__ bf16  g_xh [(size_t)MTOT * D_DIM];
__device__ bf16  g_xl [(size_t)MTOT * D_DIM];
__device__ bf16  g_wqh[(size_t)D_DIM * D_DIM];   // Wq digits (native layout)
__device__ bf16  g_wql[(size_t)D_DIM * D_DIM];
__device__ bf16  g_wkh[(size_t)D_DIM * D_DIM];   // Wk digits (native layout)
__device__ bf16  g_wkl[(size_t)D_DIM * D_DIM];
__device__ bf16  g_wvth[(size_t)D_DIM * D_DIM];  // Wv^T digits
__device__ bf16  g_wvtl[(size_t)D_DIM * D_DIM];
__device__ bf16  g_mh [(size_t)D_DIM * D_DIM];   // M' = Wk Wq^T digits
__device__ bf16  g_ml [(size_t)D_DIM * D_DIM];
__device__ bf16  g_th [(size_t)MTOT * D_DIM];    // T = x M'^T digits
__device__ bf16  g_tl [(size_t)MTOT * D_DIM];
__device__ float g_v  [(size_t)MTOT * D_DIM];
__device__ bf16  g_vth[(size_t)BATCH * D_DIM * S_LEN];  // V^T per batch
__device__ bf16  g_vtl[(size_t)BATCH * D_DIM * S_LEN];
__device__ float g_sc [(size_t)BATCH * S_LEN * S_LEN];
__device__ bf16  g_wh [(size_t)BATCH * S_LEN * S_LEN];
__device__ bf16  g_wl [(size_t)BATCH * S_LEN * S_LEN];

// ============================ PTX helpers ===================================
__device__ __forceinline__ uint32_t smem_u32(const void* p) {
    uint32_t a;
    asm("{ .reg .u64 t; cvta.to.shared.u64 t, %1; cvt.u32.u64 %0, t; }" : "=r"(a) : "l"(p));
    return a;
}
__device__ __forceinline__ void cp16(uint32_t s, const void* g) {
    asm volatile("cp.async.cg.shared.global [%0], [%1], 16;" :: "r"(s), "l"(g) : "memory");
}
#define CP_COMMIT() asm volatile("cp.async.commit_group;" ::: "memory")
#define CP_WAIT(n)  asm volatile("cp.async.wait_group %0;" :: "n"(n) : "memory")

__device__ __forceinline__ void ldm4(uint32_t r[4], uint32_t a) {
    asm volatile("ldmatrix.sync.aligned.m8n8.x4.shared.b16 {%0,%1,%2,%3}, [%4];"
                 : "=r"(r[0]), "=r"(r[1]), "=r"(r[2]), "=r"(r[3]) : "r"(a));
}
__device__ __forceinline__ void mma16816(float c[4], const uint32_t a[4], const uint32_t b[2]) {
    asm volatile("mma.sync.aligned.m16n8k16.row.col.f32.bf16.bf16.f32 "
                 "{%0,%1,%2,%3}, {%4,%5,%6,%7}, {%8,%9}, {%0,%1,%2,%3};"
                 : "+f"(c[0]), "+f"(c[1]), "+f"(c[2]), "+f"(c[3])
                 : "r"(a[0]), "r"(a[1]), "r"(a[2]), "r"(a[3]), "r"(b[0]), "r"(b[1]));
}

// ====================== split-bf16 HMMA GEMM core ===========================
// C[M,N] = (Ah+Al)[M,K] * (Bh+Bl)[N,K]^T   (all K-major bf16)
// CTA tile 128x128xBK32, 128 threads, 4 warps of 64x64, 2 CTAs/SM.
// XOR chunk swizzle on 64B rows: phys_chunk = c ^ ((row>>1)&3).
constexpr int ROW_B  = 64;
constexpr int COMP_B = 128 * ROW_B;   // 8192 B per component tile
constexpr int STG_B  = 4 * COMP_B;    // 32768 B (Ah,Al,Bh,Bl)
constexpr int NSTG   = 3;
constexpr int SMEM_SZ = NSTG * STG_B; // 98304 B -> 2 CTAs/SM

__device__ __forceinline__ void load_stage(uint32_t base,
    const bf16* __restrict__ ah, const bf16* __restrict__ al,
    const bf16* __restrict__ bh, const bf16* __restrict__ bl,
    int bm, int bn, int kt, int K, int tid)
{
    const int r  = tid >> 2;
    const int c  = tid & 3;
    const int kc = kt * 32 + c * 8;
    const int cp = c ^ ((r >> 1) & 3);
#pragma unroll
    for (int g = 0; g < 4; g++) {
        const int row = r + g * 32;
        const uint32_t so = (uint32_t)row * ROW_B + cp * 16;
        const long ga = (long)(bm + row) * K + kc;
        const long gb = (long)(bn + row) * K + kc;
        cp16(base + so,              ah + ga);
        cp16(base + COMP_B + so,     al + ga);
        cp16(base + 2 * COMP_B + so, bh + gb);
        cp16(base + 3 * COMP_B + so, bl + gb);
    }
}

__device__ __forceinline__ void gemm_core(
    uint32_t sb, int tid,
    const bf16* __restrict__ Ah, const bf16* __restrict__ Al,
    const bf16* __restrict__ Bh, const bf16* __restrict__ Bl,
    int bm, int bn, int N, int K,
    bool splitOut, float* __restrict__ C,
    bf16* __restrict__ Ch, bf16* __restrict__ Cl, long coff)
{
    const int lane = tid & 31, warp = tid >> 5;
    const int wm = warp >> 1, wn = warp & 1;
    const int nk = K >> 5;

    const uint32_t aRow = (uint32_t)(wm * 64 + (lane & 15));
    const uint32_t aSw  = (aRow >> 1) & 3;
    const uint32_t aC0  = (uint32_t)((lane >> 4) & 1);
    const uint32_t bRow0 = (uint32_t)((lane & 7) | (((lane >> 4) & 1) << 3));
    const uint32_t bRow = (uint32_t)(wn * 64) + bRow0;
    const uint32_t bSw  = (bRow0 >> 1) & 3;
    const uint32_t bC0  = (uint32_t)((lane >> 3) & 1);

    float acc[4][8][4];
#pragma unroll
    for (int i = 0; i < 4; i++)
#pragma unroll
        for (int j = 0; j < 8; j++)
#pragma unroll
            for (int q = 0; q < 4; q++) acc[i][j][q] = 0.0f;

#pragma unroll
    for (int s = 0; s < NSTG - 1; s++) {
        load_stage(sb + s * STG_B, Ah, Al, Bh, Bl, bm, bn, s, K, tid);
        CP_COMMIT();
    }

    for (int kt = 0; kt < nk; kt++) {
        CP_WAIT(NSTG - 2);
        __syncthreads();

        const int nx = kt + NSTG - 1;
        if (nx < nk)
            load_stage(sb + (nx % NSTG) * STG_B, Ah, Al, Bh, Bl, bm, bn, nx, K, tid);
        CP_COMMIT();

        const uint32_t st = sb + (kt % NSTG) * STG_B;
#pragma unroll
        for (int k16 = 0; k16 < 2; k16++) {
            const uint32_t aCk = ((uint32_t)(k16 * 2) + aC0) ^ aSw;
            const uint32_t bCk = ((uint32_t)(k16 * 2) + bC0) ^ bSw;
            const uint32_t aAddr = st + aRow * ROW_B + aCk * 16;
            const uint32_t bAddr = st + 2 * COMP_B + bRow * ROW_B + bCk * 16;
            uint32_t ah[4][4], al[4][4], bh[4][4], bl[4][4];
#pragma unroll
            for (int mi = 0; mi < 4; mi++) {
                ldm4(ah[mi], aAddr + mi * 16 * ROW_B);
                ldm4(al[mi], aAddr + COMP_B + mi * 16 * ROW_B);
            }
#pragma unroll
            for (int nb = 0; nb < 4; nb++) {
                ldm4(bh[nb], bAddr + nb * 16 * ROW_B);
                ldm4(bl[nb], bAddr + COMP_B + nb * 16 * ROW_B);
            }
#pragma unroll
            for (int mi = 0; mi < 4; mi++)
#pragma unroll
                for (int ni = 0; ni < 8; ni++) {
                    const uint32_t* bhp = &bh[ni >> 1][(ni & 1) * 2];
                    const uint32_t* blp = &bl[ni >> 1][(ni & 1) * 2];
                    mma16816(acc[mi][ni], ah[mi], bhp);  // hi*hi
                    mma16816(acc[mi][ni], ah[mi], blp);  // hi*lo
                    mma16816(acc[mi][ni], al[mi], bhp);  // lo*hi
                }
        }
    }

    // ---- epilogue ----
    const int qr = lane >> 2, qc = (lane & 3) * 2;
#pragma unroll
    for (int mi = 0; mi < 4; mi++)
#pragma unroll
        for (int ni = 0; ni < 8; ni++) {
            const int m = bm + wm * 64 + mi * 16 + qr;
            const int n = bn + wn * 64 + ni * 8 + qc;
            const long o0 = coff + (long)m * N + n;
            const long o1 = o0 + 8L * N;
            if (!splitOut) {
                *(float2*)(C + o0) = make_float2(acc[mi][ni][0], acc[mi][ni][1]);
                *(float2*)(C + o1) = make_float2(acc[mi][ni][2], acc[mi][ni][3]);
            } else {
                float x0 = acc[mi][ni][0], y0 = acc[mi][ni][1];
                float x1 = acc[mi][ni][2], y1 = acc[mi][ni][3];
                bf16 hx0 = __float2bfloat16(x0), hy0 = __float2bfloat16(y0);
                bf16 hx1 = __float2bfloat16(x1), hy1 = __float2bfloat16(y1);
                *(__nv_bfloat162*)(Ch + o0) = __nv_bfloat162(hx0, hy0);
                *(__nv_bfloat162*)(Ch + o1) = __nv_bfloat162(hx1, hy1);
                *(__nv_bfloat162*)(Cl + o0) = __nv_bfloat162(
                    __float2bfloat16(x0 - __bfloat162float(hx0)),
                    __float2bfloat16(y0 - __bfloat162float(hy0)));
                *(__nv_bfloat162*)(Cl + o1) = __nv_bfloat162(
                    __float2bfloat16(x1 - __bfloat162float(hx1)),
                    __float2bfloat16(y1 - __bfloat162float(hy1)));
            }
        }
}

// batched GEMM over blockIdx.{x,y,z}
template <bool SPLIT>
__global__ void __launch_bounds__(128, 2)
gemm_b(const bf16* __restrict__ Agh, const bf16* __restrict__ Agl,
       const bf16* __restrict__ Bgh, const bf16* __restrict__ Bgl,
       float* __restrict__ C, bf16* __restrict__ Ch, bf16* __restrict__ Cl,
       int N, int K, long sA, long sB, long sC)
{
    extern __shared__ __align__(128) char smem[];
    const int z = blockIdx.z;
    gemm_core(smem_u32(smem), threadIdx.x,
              Agh + (long)z * sA, Agl + (long)z * sA,
              Bgh + (long)z * sB, Bgl + (long)z * sB,
              blockIdx.y * 128, blockIdx.x * 128, N, K,
              SPLIT, C, Ch, Cl, (long)z * sC);
}

// combined launch: jobs [0,512) = V projection (x * Wv^T -> fp32 V),
//                  jobs [512,576) = M' = Wk * Wq^T -> split digits
__global__ void __launch_bounds__(128, 2)
gemm_vm(const bf16* __restrict__ xh, const bf16* __restrict__ xl,
        const bf16* __restrict__ wvth, const bf16* __restrict__ wvtl,
        const bf16* __restrict__ wkh, const bf16* __restrict__ wkl,
        const bf16* __restrict__ wqh, const bf16* __restrict__ wql,
        float* __restrict__ V, bf16* __restrict__ Mh, bf16* __restrict__ Ml)
{
    extern __shared__ __align__(128) char smem[];
    const int job = blockIdx.x;
    const bf16 *Ah, *Al, *Bh, *Bl;
    float* C = nullptr;
    bf16 *Ch = nullptr, *Cl = nullptr;
    bool sp;
    int bm, bn;
    if (job < 512) {
        bm = (job >> 3) * 128; bn = (job & 7) * 128;
        Ah = xh; Al = xl; Bh = wvth; Bl = wvtl;
        C = V; sp = false;
    } else {
        const int j = job - 512;
        bm = (j >> 3) * 128; bn = (j & 7) * 128;
        Ah = wkh; Al = wkl; Bh = wqh; Bl = wql;
        Ch = Mh; Cl = Ml; sp = true;
    }
    gemm_core(smem_u32(smem), threadIdx.x, Ah, Al, Bh, Bl,
              bm, bn, D_DIM, D_DIM, sp, C, Ch, Cl, 0);
}

// =========================== prep kernels ===================================
__global__ void split_f32(const float* __restrict__ in, bf16* __restrict__ oh,
                          bf16* __restrict__ ol)
{
    long i = ((long)blockIdx.x * 256 + threadIdx.x) * 4;
    float4 f = *(const float4*)(in + i);
    bf16 h0 = __float2bfloat16(f.x), h1 = __float2bfloat16(f.y);
    bf16 h2 = __float2bfloat16(f.z), h3 = __float2bfloat16(f.w);
    __nv_bfloat162* hp = (__nv_bfloat162*)(oh + i);
    __nv_bfloat162* lp = (__nv_bfloat162*)(ol + i);
    hp[0] = __nv_bfloat162(h0, h1);
    hp[1] = __nv_bfloat162(h2, h3);
    lp[0] = __nv_bfloat162(__float2bfloat16(f.x - __bfloat162float(h0)),
                           __float2bfloat16(f.y - __bfloat162float(h1)));
    lp[1] = __nv_bfloat162(__float2bfloat16(f.z - __bfloat162float(h2)),
                           __float2bfloat16(f.w - __bfloat162float(h3)));
}

// transpose [rows,C] -> [C,rows] with hi/lo bf16 split; z batches via strides
__global__ void tsplit(const float* __restrict__ in, bf16* __restrict__ oh,
                       bf16* __restrict__ ol, int R, int C, long sIn, long sOut)
{
    __shared__ float t[32][33];
    const int bx = blockIdx.x * 32, by = blockIdx.y * 32;
    const float* ip = in + (long)blockIdx.z * sIn;
    bf16* ohp = oh + (long)blockIdx.z * sOut;
    bf16* olp = ol + (long)blockIdx.z * sOut;
    const int tx = threadIdx.x;
#pragma unroll
    for (int i = threadIdx.y; i < 32; i += 8)
        t[i][tx] = ip[(long)(by + i) * C + bx + tx];
    __syncthreads();
#pragma unroll
    for (int i = threadIdx.y; i < 32; i += 8) {
        float f = t[tx][i];
        bf16 h = __float2bfloat16(f);
        long o = (long)(bx + i) * R + by + tx;
        ohp[o] = h;
        olp[o] = __float2bfloat16(f - __bfloat162float(h));
    }
}

// ============================ softmax =======================================
__device__ __forceinline__ float warpMax(float v) {
#pragma unroll
    for (int o = 16; o; o >>= 1) v = fmaxf(v, __shfl_xor_sync(0xFFFFFFFFu, v, o));
    return v;
}
__device__ __forceinline__ float warpSum(float v) {
#pragma unroll
    for (int o = 16; o; o >>= 1) v += __shfl_xor_sync(0xFFFFFFFFu, v, o);
    return v;
}

struct alignas(8) bf16x4 { __nv_bfloat162 a, b; };

__global__ void softmax_rows(const float* __restrict__ Sc,
                             bf16* __restrict__ Wh, bf16* __restrict__ Wl)
{
    __shared__ float red[8];
    const long row = blockIdx.x;
    const float4* p4 = (const float4*)(Sc + row * (long)S_LEN);
    const int tid = threadIdx.x;
    const float scale = 0.03125f;  // 1/sqrt(1024)

    float4 va = p4[tid], vb = p4[tid + 256];
    float v[8] = {va.x, va.y, va.z, va.w, vb.x, vb.y, vb.z, vb.w};
    float mx = -3.402823e38f;
#pragma unroll
    for (int i = 0; i < 8; i++) { v[i] *= scale; mx = fmaxf(mx, v[i]); }
    mx = warpMax(mx);
    if ((tid & 31) == 0) red[tid >> 5] = mx;
    __syncthreads();
    if (tid < 32) {
        float m = (tid < 8) ? red[tid] : -3.402823e38f;
        m = warpMax(m);
        if (tid == 0) red[0] = m;
    }
    __syncthreads();
    mx = red[0];
    __syncthreads();

    float s = 0.0f;
#pragma unroll
    for (int i = 0; i < 8; i++) { v[i] = __expf(v[i] - mx); s += v[i]; }
    s = warpSum(s);
    if ((tid & 31) == 0) red[tid >> 5] = s;
    __syncthreads();
    if (tid < 32) {
        float t = (tid < 8) ? red[tid] : 0.0f;
        t = warpSum(t);
        if (tid == 0) red[0] = t;
    }
    __syncthreads();
    const float inv = 1.0f / red[0];

    bf16 h[8], l[8];
#pragma unroll
    for (int i = 0; i < 8; i++) {
        float w = v[i] * inv;
        h[i] = __float2bfloat16(w);
        l[i] = __float2bfloat16(w - __bfloat162float(h[i]));
    }
    bf16x4* wh4 = (bf16x4*)(Wh + row * (long)S_LEN);
    bf16x4* wl4 = (bf16x4*)(Wl + row * (long)S_LEN);
    wh4[tid]       = {__nv_bfloat162(h[0], h[1]), __nv_bfloat162(h[2], h[3])};
    wh4[tid + 256] = {__nv_bfloat162(h[4], h[5]), __nv_bfloat162(h[6], h[7])};
    wl4[tid]       = {__nv_bfloat162(l[0], l[1]), __nv_bfloat162(l[2], l[3])};
    wl4[tid + 256] = {__nv_bfloat162(l[4], l[5]), __nv_bfloat162(l[6], l[7])};
}

// ============================ host side =====================================
extern "C" void kernel_launch(void* const* d_in, const int* in_sizes, int n_in,
                              void* d_out, int out_size)
{
    const float* x  = (const float*)d_in[0];
    const float* Wq = (const float*)d_in[1];
    const float* Wk = (const float*)d_in[2];
    const float* Wv = (const float*)d_in[3];
    float* out = (float*)d_out;

    void *xh, *xl, *wqh, *wql, *wkh, *wkl, *wvth, *wvtl, *mh, *ml, *th, *tl;
    void *v, *vth, *vtl, *sc, *wh, *wl;
    cudaGetSymbolAddress(&xh, g_xh);     cudaGetSymbolAddress(&xl, g_xl);
    cudaGetSymbolAddress(&wqh, g_wqh);   cudaGetSymbolAddress(&wql, g_wql);
    cudaGetSymbolAddress(&wkh, g_wkh);   cudaGetSymbolAddress(&wkl, g_wkl);
    cudaGetSymbolAddress(&wvth, g_wvth); cudaGetSymbolAddress(&wvtl, g_wvtl);
    cudaGetSymbolAddress(&mh, g_mh);     cudaGetSymbolAddress(&ml, g_ml);
    cudaGetSymbolAddress(&th, g_th);     cudaGetSymbolAddress(&tl, g_tl);
    cudaGetSymbolAddress(&v, g_v);
    cudaGetSymbolAddress(&vth, g_vth);   cudaGetSymbolAddress(&vtl, g_vtl);
    cudaGetSymbolAddress(&sc, g_sc);
    cudaGetSymbolAddress(&wh, g_wh);     cudaGetSymbolAddress(&wl, g_wl);

    cudaFuncSetAttribute(gemm_b<false>, cudaFuncAttributeMaxDynamicSharedMemorySize, SMEM_SZ);
    cudaFuncSetAttribute(gemm_b<true>,  cudaFuncAttributeMaxDynamicSharedMemorySize, SMEM_SZ);
    cudaFuncSetAttribute(gemm_vm,       cudaFuncAttributeMaxDynamicSharedMemorySize, SMEM_SZ);

    const long SD = (long)S_LEN * D_DIM, SS = (long)S_LEN * S_LEN;
    dim3 tb(32, 8);

    // ---- data prep ----
    split_f32<<<(int)((long)MTOT * D_DIM / 1024), 256>>>(x, (bf16*)xh, (bf16*)xl);
    split_f32<<<(int)((long)D_DIM * D_DIM / 1024), 256>>>(Wq, (bf16*)wqh, (bf16*)wql);
    split_f32<<<(int)((long)D_DIM * D_DIM / 1024), 256>>>(Wk, (bf16*)wkh, (bf16*)wkl);
    tsplit<<<dim3(D_DIM / 32, D_DIM / 32, 1), tb>>>(Wv, (bf16*)wvth, (bf16*)wvtl,
                                                    D_DIM, D_DIM, 0, 0);

    // ---- combined: V = x Wv^T (fp32)  +  M' = Wk Wq^T (split digits) ----
    gemm_vm<<<576, 128, SMEM_SZ>>>((bf16*)xh, (bf16*)xl, (bf16*)wvth, (bf16*)wvtl,
                                   (bf16*)wkh, (bf16*)wkl, (bf16*)wqh, (bf16*)wql,
                                   (float*)v, (bf16*)mh, (bf16*)ml);

    // V -> V^T hi/lo per batch
    tsplit<<<dim3(D_DIM / 32, S_LEN / 32, BATCH), tb>>>(
        (const float*)v, (bf16*)vth, (bf16*)vtl, S_LEN, D_DIM, SD, SD);

    // ---- T = x M'^T (split digits) ----
    gemm_b<true><<<dim3(D_DIM / 128, MTOT / 128, 1), 128, SMEM_SZ>>>(
        (bf16*)xh, (bf16*)xl, (bf16*)mh, (bf16*)ml,
        nullptr, (bf16*)th, (bf16*)tl, D_DIM, D_DIM, 0, 0, 0);

    // ---- scores = T x^T per batch ----
    gemm_b<false><<<dim3(S_LEN / 128, S_LEN / 128, BATCH), 128, SMEM_SZ>>>(
        (bf16*)th, (bf16*)tl, (bf16*)xh, (bf16*)xl,
        (float*)sc, nullptr, nullptr, S_LEN, D_DIM, SD, SD, SS);

    softmax_rows<<<BATCH * S_LEN, 256>>>((const float*)sc, (bf16*)wh, (bf16*)wl);

    // ---- out = softmaxW * V ----
    gemm_b<false><<<dim3(D_DIM / 128, S_LEN / 128, BATCH), 128, SMEM_SZ>>>(
        (bf16*)wh, (bf16*)wl, (bf16*)vth, (bf16*)vtl,
        out, nullptr, nullptr, D_DIM, S_LEN, SS, SD, SD);
}

// round 11
// speedup vs baseline: 3.7851x; 1.0211x over previous
#include <cuda_runtime.h>
#include <cuda_bf16.h>
#include <cstdint>

#define S_LEN 2048
#define D_DIM 1024
#define BATCH 4
#define MTOT  (BATCH * S_LEN)   // 8192

typedef __nv_bfloat16 bf16;

// ============================ device scratch ================================
__device__ bf16  g_xh [(size_t)MTOT * D_DIM];
__device__ bf16  g_xl [(size_t)MTOT * D_DIM];
__device__ bf16  g_wqh[(size_t)D_DIM * D_DIM];   // Wq digits (native layout)
__device__ bf16  g_wql[(size_t)D_DIM * D_DIM];
__device__ bf16  g_wkh[(size_t)D_DIM * D_DIM];   // Wk digits (native layout)
__device__ bf16  g_wkl[(size_t)D_DIM * D_DIM];
__device__ bf16  g_wvth[(size_t)D_DIM * D_DIM];  // Wv^T digits
__device__ bf16  g_wvtl[(size_t)D_DIM * D_DIM];
__device__ bf16  g_mh [(size_t)D_DIM * D_DIM];   // M' = Wk Wq^T digits
__device__ bf16  g_ml [(size_t)D_DIM * D_DIM];
__device__ bf16  g_th [(size_t)MTOT * D_DIM];    // T = x M'^T digits
__device__ bf16  g_tl [(size_t)MTOT * D_DIM];
__device__ bf16  g_vth[(size_t)BATCH * D_DIM * S_LEN];  // V^T digits per batch
__device__ bf16  g_vtl[(size_t)BATCH * D_DIM * S_LEN];
__device__ float g_sc [(size_t)BATCH * S_LEN * S_LEN];
__device__ bf16  g_wh [(size_t)BATCH * S_LEN * S_LEN];
__device__ bf16  g_wl [(size_t)BATCH * S_LEN * S_LEN];

// ============================ PTX helpers ===================================
__device__ __forceinline__ uint32_t smem_u32(const void* p) {
    uint32_t a;
    asm("{ .reg .u64 t; cvta.to.shared.u64 t, %1; cvt.u32.u64 %0, t; }" : "=r"(a) : "l"(p));
    return a;
}
__device__ __forceinline__ void cp16(uint32_t s, const void* g) {
    asm volatile("cp.async.cg.shared.global [%0], [%1], 16;" :: "r"(s), "l"(g) : "memory");
}
#define CP_COMMIT() asm volatile("cp.async.commit_group;" ::: "memory")
#define CP_WAIT(n)  asm volatile("cp.async.wait_group %0;" :: "n"(n) : "memory")

__device__ __forceinline__ void ldm4(uint32_t r[4], uint32_t a) {
    asm volatile("ldmatrix.sync.aligned.m8n8.x4.shared.b16 {%0,%1,%2,%3}, [%4];"
                 : "=r"(r[0]), "=r"(r[1]), "=r"(r[2]), "=r"(r[3]) : "r"(a));
}
__device__ __forceinline__ void mma16816(float c[4], const uint32_t a[4], const uint32_t b[2]) {
    asm volatile("mma.sync.aligned.m16n8k16.row.col.f32.bf16.bf16.f32 "
                 "{%0,%1,%2,%3}, {%4,%5,%6,%7}, {%8,%9}, {%0,%1,%2,%3};"
                 : "+f"(c[0]), "+f"(c[1]), "+f"(c[2]), "+f"(c[3])
                 : "r"(a[0]), "r"(a[1]), "r"(a[2]), "r"(a[3]), "r"(b[0]), "r"(b[1]));
}

// ====================== split-bf16 HMMA GEMM core ===========================
// C[M,N] = (Ah+Al)[M,K] * (Bh+Bl)[N,K]^T   (all K-major bf16)
// CTA tile 128x128xBK32, 128 threads, 4 warps of 64x64, 2 CTAs/SM.
// XOR chunk swizzle on 64B rows: phys_chunk = c ^ ((row>>1)&3).
constexpr int ROW_B  = 64;
constexpr int COMP_B = 128 * ROW_B;   // 8192 B per component tile
constexpr int STG_B  = 4 * COMP_B;    // 32768 B (Ah,Al,Bh,Bl)
constexpr int NSTG   = 3;
constexpr int SMEM_SZ = NSTG * STG_B; // 98304 B -> 2 CTAs/SM
constexpr int TPAD   = 133;           // fp32 transpose-buffer row stride (words)

__device__ __forceinline__ void load_stage(uint32_t base,
    const bf16* __restrict__ ah, const bf16* __restrict__ al,
    const bf16* __restrict__ bh, const bf16* __restrict__ bl,
    int bm, int bn, int kt, int K, int tid)
{
    const int r  = tid >> 2;
    const int c  = tid & 3;
    const int kc = kt * 32 + c * 8;
    const int cp = c ^ ((r >> 1) & 3);
#pragma unroll
    for (int g = 0; g < 4; g++) {
        const int row = r + g * 32;
        const uint32_t so = (uint32_t)row * ROW_B + cp * 16;
        const long ga = (long)(bm + row) * K + kc;
        const long gb = (long)(bn + row) * K + kc;
        cp16(base + so,              ah + ga);
        cp16(base + COMP_B + so,     al + ga);
        cp16(base + 2 * COMP_B + so, bh + gb);
        cp16(base + 3 * COMP_B + so, bl + gb);
    }
}

// epi: 0 = fp32 C @ coff; 1 = split digits Ch/Cl @ coff;
//      2 = V^T transposed split: Ch/Cl are [BATCH][D_DIM][S_LEN] digit arrays,
//          batch/offset derived from bm (M = batch*seq), columns from bn.
__device__ __forceinline__ void gemm_core(
    uint32_t sb, float* __restrict__ tsbuf, int tid,
    const bf16* __restrict__ Ah, const bf16* __restrict__ Al,
    const bf16* __restrict__ Bh, const bf16* __restrict__ Bl,
    int bm, int bn, int N, int K,
    int epi, float* __restrict__ C,
    bf16* __restrict__ Ch, bf16* __restrict__ Cl, long coff)
{
    const int lane = tid & 31, warp = tid >> 5;
    const int wm = warp >> 1, wn = warp & 1;
    const int nk = K >> 5;

    const uint32_t aRow = (uint32_t)(wm * 64 + (lane & 15));
    const uint32_t aSw  = (aRow >> 1) & 3;
    const uint32_t aC0  = (uint32_t)((lane >> 4) & 1);
    const uint32_t bRow0 = (uint32_t)((lane & 7) | (((lane >> 4) & 1) << 3));
    const uint32_t bRow = (uint32_t)(wn * 64) + bRow0;
    const uint32_t bSw  = (bRow0 >> 1) & 3;
    const uint32_t bC0  = (uint32_t)((lane >> 3) & 1);

    float acc[4][8][4];
#pragma unroll
    for (int i = 0; i < 4; i++)
#pragma unroll
        for (int j = 0; j < 8; j++)
#pragma unroll
            for (int q = 0; q < 4; q++) acc[i][j][q] = 0.0f;

#pragma unroll
    for (int s = 0; s < NSTG - 1; s++) {
        load_stage(sb + s * STG_B, Ah, Al, Bh, Bl, bm, bn, s, K, tid);
        CP_COMMIT();
    }

    for (int kt = 0; kt < nk; kt++) {
        CP_WAIT(NSTG - 2);
        __syncthreads();

        const int nx = kt + NSTG - 1;
        if (nx < nk)
            load_stage(sb + (nx % NSTG) * STG_B, Ah, Al, Bh, Bl, bm, bn, nx, K, tid);
        CP_COMMIT();

        const uint32_t st = sb + (kt % NSTG) * STG_B;
#pragma unroll
        for (int k16 = 0; k16 < 2; k16++) {
            const uint32_t aCk = ((uint32_t)(k16 * 2) + aC0) ^ aSw;
            const uint32_t bCk = ((uint32_t)(k16 * 2) + bC0) ^ bSw;
            const uint32_t aAddr = st + aRow * ROW_B + aCk * 16;
            const uint32_t bAddr = st + 2 * COMP_B + bRow * ROW_B + bCk * 16;
            uint32_t ah[4][4], al[4][4], bh[4][4], bl[4][4];
#pragma unroll
            for (int mi = 0; mi < 4; mi++) {
                ldm4(ah[mi], aAddr + mi * 16 * ROW_B);
                ldm4(al[mi], aAddr + COMP_B + mi * 16 * ROW_B);
            }
#pragma unroll
            for (int nb = 0; nb < 4; nb++) {
                ldm4(bh[nb], bAddr + nb * 16 * ROW_B);
                ldm4(bl[nb], bAddr + COMP_B + nb * 16 * ROW_B);
            }
#pragma unroll
            for (int mi = 0; mi < 4; mi++)
#pragma unroll
                for (int ni = 0; ni < 8; ni++) {
                    const uint32_t* bhp = &bh[ni >> 1][(ni & 1) * 2];
                    const uint32_t* blp = &bl[ni >> 1][(ni & 1) * 2];
                    mma16816(acc[mi][ni], ah[mi], bhp);  // hi*hi
                    mma16816(acc[mi][ni], ah[mi], blp);  // hi*lo
                    mma16816(acc[mi][ni], al[mi], bhp);  // lo*hi
                }
        }
    }

    const int qr = lane >> 2, qc = (lane & 3) * 2;

    if (epi == 2) {
        // ---- transposed split epilogue (V^T digits) ----
        __syncthreads();   // all warps done reading the last stage before reuse
#pragma unroll
        for (int mi = 0; mi < 4; mi++)
#pragma unroll
            for (int ni = 0; ni < 8; ni++) {
                const int m = wm * 64 + mi * 16 + qr;
                const int n = wn * 64 + ni * 8 + qc;
                tsbuf[m * TPAD + n]           = acc[mi][ni][0];
                tsbuf[m * TPAD + n + 1]       = acc[mi][ni][1];
                tsbuf[(m + 8) * TPAD + n]     = acc[mi][ni][2];
                tsbuf[(m + 8) * TPAD + n + 1] = acc[mi][ni][3];
            }
        __syncthreads();
        const long DS = (long)D_DIM * S_LEN;
        const int zb = bm >> 11;              // batch  (bm multiple of 128, tiles don't straddle)
        const int mloc = bm & 2047;           // seq offset within batch
        bf16* oh = Ch + (long)zb * DS;
        bf16* ol = Cl + (long)zb * DS;
        for (int k = 0; k < 32; k++) {
            const int n = warp + 4 * k;       // local output row (headdim)
            const long base = (long)(bn + n) * S_LEN + mloc;
#pragma unroll
            for (int j = 0; j < 4; j++) {
                const int m = lane + 32 * j;
                float f = tsbuf[m * TPAD + n];      // bank 5*lane mod 32: conflict-free
                bf16 h = __float2bfloat16(f);
                oh[base + m] = h;                    // 2B coalesced across lanes
                ol[base + m] = __float2bfloat16(f - __bfloat162float(h));
            }
        }
        return;
    }

#pragma unroll
    for (int mi = 0; mi < 4; mi++)
#pragma unroll
        for (int ni = 0; ni < 8; ni++) {
            const int m = bm + wm * 64 + mi * 16 + qr;
            const int n = bn + wn * 64 + ni * 8 + qc;
            const long o0 = coff + (long)m * N + n;
            const long o1 = o0 + 8L * N;
            if (epi == 0) {
                *(float2*)(C + o0) = make_float2(acc[mi][ni][0], acc[mi][ni][1]);
                *(float2*)(C + o1) = make_float2(acc[mi][ni][2], acc[mi][ni][3]);
            } else {
                float x0 = acc[mi][ni][0], y0 = acc[mi][ni][1];
                float x1 = acc[mi][ni][2], y1 = acc[mi][ni][3];
                bf16 hx0 = __float2bfloat16(x0), hy0 = __float2bfloat16(y0);
                bf16 hx1 = __float2bfloat16(x1), hy1 = __float2bfloat16(y1);
                *(__nv_bfloat162*)(Ch + o0) = __nv_bfloat162(hx0, hy0);
                *(__nv_bfloat162*)(Ch + o1) = __nv_bfloat162(hx1, hy1);
                *(__nv_bfloat162*)(Cl + o0) = __nv_bfloat162(
                    __float2bfloat16(x0 - __bfloat162float(hx0)),
                    __float2bfloat16(y0 - __bfloat162float(hy0)));
                *(__nv_bfloat162*)(Cl + o1) = __nv_bfloat162(
                    __float2bfloat16(x1 - __bfloat162float(hx1)),
                    __float2bfloat16(y1 - __bfloat162float(hy1)));
            }
        }
}

// batched GEMM over blockIdx.{x,y,z}
template <bool SPLIT>
__global__ void __launch_bounds__(128, 2)
gemm_b(const bf16* __restrict__ Agh, const bf16* __restrict__ Agl,
       const bf16* __restrict__ Bgh, const bf16* __restrict__ Bgl,
       float* __restrict__ C, bf16* __restrict__ Ch, bf16* __restrict__ Cl,
       int N, int K, long sA, long sB, long sC)
{
    extern __shared__ __align__(128) char smem[];
    const int z = blockIdx.z;
    gemm_core(smem_u32(smem), (float*)smem, threadIdx.x,
              Agh + (long)z * sA, Agl + (long)z * sA,
              Bgh + (long)z * sB, Bgl + (long)z * sB,
              blockIdx.y * 128, blockIdx.x * 128, N, K,
              SPLIT ? 1 : 0, C, Ch, Cl, (long)z * sC);
}

// combined launch: jobs [0,512) = V projection -> V^T digits (transposed epi),
//                  jobs [512,576) = M' = Wk * Wq^T -> split digits
__global__ void __launch_bounds__(128, 2)
gemm_vm(const bf16* __restrict__ xh, const bf16* __restrict__ xl,
        const bf16* __restrict__ wvth, const bf16* __restrict__ wvtl,
        const bf16* __restrict__ wkh, const bf16* __restrict__ wkl,
        const bf16* __restrict__ wqh, const bf16* __restrict__ wql,
        bf16* __restrict__ Vth, bf16* __restrict__ Vtl,
        bf16* __restrict__ Mh, bf16* __restrict__ Ml)
{
    extern __shared__ __align__(128) char smem[];
    const int job = blockIdx.x;
    if (job < 512) {
        const int bm = (job >> 3) * 128, bn = (job & 7) * 128;
        gemm_core(smem_u32(smem), (float*)smem, threadIdx.x,
                  xh, xl, wvth, wvtl, bm, bn, D_DIM, D_DIM,
                  2, nullptr, Vth, Vtl, 0);
    } else {
        const int j = job - 512;
        const int bm = (j >> 3) * 128, bn = (j & 7) * 128;
        gemm_core(smem_u32(smem), (float*)smem, threadIdx.x,
                  wkh, wkl, wqh, wql, bm, bn, D_DIM, D_DIM,
                  1, nullptr, Mh, Ml, 0);
    }
}

// =========================== prep kernels ===================================
__global__ void split_f32(const float* __restrict__ in, bf16* __restrict__ oh,
                          bf16* __restrict__ ol)
{
    long i = ((long)blockIdx.x * 256 + threadIdx.x) * 4;
    float4 f = *(const float4*)(in + i);
    bf16 h0 = __float2bfloat16(f.x), h1 = __float2bfloat16(f.y);
    bf16 h2 = __float2bfloat16(f.z), h3 = __float2bfloat16(f.w);
    __nv_bfloat162* hp = (__nv_bfloat162*)(oh + i);
    __nv_bfloat162* lp = (__nv_bfloat162*)(ol + i);
    hp[0] = __nv_bfloat162(h0, h1);
    hp[1] = __nv_bfloat162(h2, h3);
    lp[0] = __nv_bfloat162(__float2bfloat16(f.x - __bfloat162float(h0)),
                           __float2bfloat16(f.y - __bfloat162float(h1)));
    lp[1] = __nv_bfloat162(__float2bfloat16(f.z - __bfloat162float(h2)),
                           __float2bfloat16(f.w - __bfloat162float(h3)));
}

// fused weight prep: z=0 split Wq, z=1 split Wk, z=2 transpose+split Wv
__global__ void prepW(const float* __restrict__ Wq, const float* __restrict__ Wk,
                      const float* __restrict__ Wv,
                      bf16* __restrict__ qh, bf16* __restrict__ ql,
                      bf16* __restrict__ kh, bf16* __restrict__ kl,
                      bf16* __restrict__ vth, bf16* __restrict__ vtl)
{
    __shared__ float t[32][33];
    const int z = blockIdx.z;
    const int bx = blockIdx.x * 32, by = blockIdx.y * 32;
    const int tx = threadIdx.x;
    if (z < 2) {
        const float* ip = (z == 0) ? Wq : Wk;
        bf16* oh = (z == 0) ? qh : kh;
        bf16* ol = (z == 0) ? ql : kl;
#pragma unroll
        for (int i = threadIdx.y; i < 32; i += 8) {
            long o = (long)(by + i) * D_DIM + bx + tx;
            float f = ip[o];
            bf16 h = __float2bfloat16(f);
            oh[o] = h;
            ol[o] = __float2bfloat16(f - __bfloat162float(h));
        }
    } else {
#pragma unroll
        for (int i = threadIdx.y; i < 32; i += 8)
            t[i][tx] = Wv[(long)(by + i) * D_DIM + bx + tx];
        __syncthreads();
#pragma unroll
        for (int i = threadIdx.y; i < 32; i += 8) {
            float f = t[tx][i];
            bf16 h = __float2bfloat16(f);
            long o = (long)(bx + i) * D_DIM + by + tx;
            vth[o] = h;
            vtl[o] = __float2bfloat16(f - __bfloat162float(h));
        }
    }
}

// ============================ softmax =======================================
__device__ __forceinline__ float warpMax(float v) {
#pragma unroll
    for (int o = 16; o; o >>= 1) v = fmaxf(v, __shfl_xor_sync(0xFFFFFFFFu, v, o));
    return v;
}
__device__ __forceinline__ float warpSum(float v) {
#pragma unroll
    for (int o = 16; o; o >>= 1) v += __shfl_xor_sync(0xFFFFFFFFu, v, o);
    return v;
}

struct alignas(8) bf16x4 { __nv_bfloat162 a, b; };

__global__ void softmax_rows(const float* __restrict__ Sc,
                             bf16* __restrict__ Wh, bf16* __restrict__ Wl)
{
    __shared__ float red[8];
    const long row = blockIdx.x;
    const float4* p4 = (const float4*)(Sc + row * (long)S_LEN);
    const int tid = threadIdx.x;
    const float scale = 0.03125f;  // 1/sqrt(1024)

    float4 va = p4[tid], vb = p4[tid + 256];
    float v[8] = {va.x, va.y, va.z, va.w, vb.x, vb.y, vb.z, vb.w};
    float mx = -3.402823e38f;
#pragma unroll
    for (int i = 0; i < 8; i++) { v[i] *= scale; mx = fmaxf(mx, v[i]); }
    mx = warpMax(mx);
    if ((tid & 31) == 0) red[tid >> 5] = mx;
    __syncthreads();
    if (tid < 32) {
        float m = (tid < 8) ? red[tid] : -3.402823e38f;
        m = warpMax(m);
        if (tid == 0) red[0] = m;
    }
    __syncthreads();
    mx = red[0];
    __syncthreads();

    float s = 0.0f;
#pragma unroll
    for (int i = 0; i < 8; i++) { v[i] = __expf(v[i] - mx); s += v[i]; }
    s = warpSum(s);
    if ((tid & 31) == 0) red[tid >> 5] = s;
    __syncthreads();
    if (tid < 32) {
        float t = (tid < 8) ? red[tid] : 0.0f;
        t = warpSum(t);
        if (tid == 0) red[0] = t;
    }
    __syncthreads();
    const float inv = 1.0f / red[0];

    bf16 h[8], l[8];
#pragma unroll
    for (int i = 0; i < 8; i++) {
        float w = v[i] * inv;
        h[i] = __float2bfloat16(w);
        l[i] = __float2bfloat16(w - __bfloat162float(h[i]));
    }
    bf16x4* wh4 = (bf16x4*)(Wh + row * (long)S_LEN);
    bf16x4* wl4 = (bf16x4*)(Wl + row * (long)S_LEN);
    wh4[tid]       = {__nv_bfloat162(h[0], h[1]), __nv_bfloat162(h[2], h[3])};
    wh4[tid + 256] = {__nv_bfloat162(h[4], h[5]), __nv_bfloat162(h[6], h[7])};
    wl4[tid]       = {__nv_bfloat162(l[0], l[1]), __nv_bfloat162(l[2], l[3])};
    wl4[tid + 256] = {__nv_bfloat162(l[4], l[5]), __nv_bfloat162(l[6], l[7])};
}

// ============================ host side =====================================
extern "C" void kernel_launch(void* const* d_in, const int* in_sizes, int n_in,
                              void* d_out, int out_size)
{
    const float* x  = (const float*)d_in[0];
    const float* Wq = (const float*)d_in[1];
    const float* Wk = (const float*)d_in[2];
    const float* Wv = (const float*)d_in[3];
    float* out = (float*)d_out;

    void *xh, *xl, *wqh, *wql, *wkh, *wkl, *wvth, *wvtl, *mh, *ml, *th, *tl;
    void *vth, *vtl, *sc, *wh, *wl;
    cudaGetSymbolAddress(&xh, g_xh);     cudaGetSymbolAddress(&xl, g_xl);
    cudaGetSymbolAddress(&wqh, g_wqh);   cudaGetSymbolAddress(&wql, g_wql);
    cudaGetSymbolAddress(&wkh, g_wkh);   cudaGetSymbolAddress(&wkl, g_wkl);
    cudaGetSymbolAddress(&wvth, g_wvth); cudaGetSymbolAddress(&wvtl, g_wvtl);
    cudaGetSymbolAddress(&mh, g_mh);     cudaGetSymbolAddress(&ml, g_ml);
    cudaGetSymbolAddress(&th, g_th);     cudaGetSymbolAddress(&tl, g_tl);
    cudaGetSymbolAddress(&vth, g_vth);   cudaGetSymbolAddress(&vtl, g_vtl);
    cudaGetSymbolAddress(&sc, g_sc);
    cudaGetSymbolAddress(&wh, g_wh);     cudaGetSymbolAddress(&wl, g_wl);

    cudaFuncSetAttribute(gemm_b<false>, cudaFuncAttributeMaxDynamicSharedMemorySize, SMEM_SZ);
    cudaFuncSetAttribute(gemm_b<true>,  cudaFuncAttributeMaxDynamicSharedMemorySize, SMEM_SZ);
    cudaFuncSetAttribute(gemm_vm,       cudaFuncAttributeMaxDynamicSharedMemorySize, SMEM_SZ);

    const long SD = (long)S_LEN * D_DIM, SS = (long)S_LEN * S_LEN;
    dim3 tb(32, 8);

    // ---- data prep ----
    split_f32<<<(int)((long)MTOT * D_DIM / 1024), 256>>>(x, (bf16*)xh, (bf16*)xl);
    prepW<<<dim3(32, 32, 3), tb>>>(Wq, Wk, Wv,
        (bf16*)wqh, (bf16*)wql, (bf16*)wkh, (bf16*)wkl, (bf16*)wvth, (bf16*)wvtl);

    // ---- combined: V^T digits (transposed epilogue)  +  M' = Wk Wq^T ----
    gemm_vm<<<576, 128, SMEM_SZ>>>((bf16*)xh, (bf16*)xl, (bf16*)wvth, (bf16*)wvtl,
                                   (bf16*)wkh, (bf16*)wkl, (bf16*)wqh, (bf16*)wql,
                                   (bf16*)vth, (bf16*)vtl, (bf16*)mh, (bf16*)ml);

    // ---- T = x M'^T (split digits) ----
    gemm_b<true><<<dim3(D_DIM / 128, MTOT / 128, 1), 128, SMEM_SZ>>>(
        (bf16*)xh, (bf16*)xl, (bf16*)mh, (bf16*)ml,
        nullptr, (bf16*)th, (bf16*)tl, D_DIM, D_DIM, 0, 0, 0);

    // ---- scores = T x^T per batch ----
    gemm_b<false><<<dim3(S_LEN / 128, S_LEN / 128, BATCH), 128, SMEM_SZ>>>(
        (bf16*)th, (bf16*)tl, (bf16*)xh, (bf16*)xl,
        (float*)sc, nullptr, nullptr, S_LEN, D_DIM, SD, SD, SS);

    softmax_rows<<<BATCH * S_LEN, 256>>>((const float*)sc, (bf16*)wh, (bf16*)wl);

    // ---- out = softmaxW * V ----
    gemm_b<false><<<dim3(D_DIM / 128, S_LEN / 128, BATCH), 128, SMEM_SZ>>>(
        (bf16*)wh, (bf16*)wl, (bf16*)vth, (bf16*)vtl,
        out, nullptr, nullptr, D_DIM, S_LEN, SS, SD, SD);
}

// round 12
// speedup vs baseline: 3.8933x; 1.0286x over previous
#include <cuda_runtime.h>
#include <cuda_bf16.h>
#include <cstdint>

#define S_LEN 2048
#define D_DIM 1024
#define BATCH 4
#define MTOT  (BATCH * S_LEN)   // 8192

typedef __nv_bfloat16 bf16;

// ============================ device scratch ================================
__device__ bf16  g_xh [(size_t)MTOT * D_DIM];
__device__ bf16  g_xl [(size_t)MTOT * D_DIM];
__device__ bf16  g_wqh[(size_t)D_DIM * D_DIM];   // Wq digits (native layout)
__device__ bf16  g_wql[(size_t)D_DIM * D_DIM];
__device__ bf16  g_wkh[(size_t)D_DIM * D_DIM];   // Wk digits (native layout)
__device__ bf16  g_wkl[(size_t)D_DIM * D_DIM];
__device__ bf16  g_wvth[(size_t)D_DIM * D_DIM];  // Wv^T digits
__device__ bf16  g_wvtl[(size_t)D_DIM * D_DIM];
__device__ bf16  g_mh [(size_t)D_DIM * D_DIM];   // M' = Wk Wq^T digits
__device__ bf16  g_ml [(size_t)D_DIM * D_DIM];
__device__ bf16  g_th [(size_t)MTOT * D_DIM];    // T = x M'^T digits
__device__ bf16  g_tl [(size_t)MTOT * D_DIM];
__device__ bf16  g_vth[(size_t)BATCH * D_DIM * S_LEN];  // V^T digits per batch
__device__ bf16  g_vtl[(size_t)BATCH * D_DIM * S_LEN];
__device__ float g_sc [(size_t)BATCH * S_LEN * S_LEN];
__device__ bf16  g_wh [(size_t)BATCH * S_LEN * S_LEN];
__device__ bf16  g_wl [(size_t)BATCH * S_LEN * S_LEN];

// ============================ PTX helpers ===================================
__device__ __forceinline__ uint32_t smem_u32(const void* p) {
    uint32_t a;
    asm("{ .reg .u64 t; cvta.to.shared.u64 t, %1; cvt.u32.u64 %0, t; }" : "=r"(a) : "l"(p));
    return a;
}
__device__ __forceinline__ void cp16(uint32_t s, const void* g) {
    asm volatile("cp.async.cg.shared.global [%0], [%1], 16;" :: "r"(s), "l"(g) : "memory");
}
#define CP_COMMIT() asm volatile("cp.async.commit_group;" ::: "memory")
#define CP_WAIT(n)  asm volatile("cp.async.wait_group %0;" :: "n"(n) : "memory")

__device__ __forceinline__ void ldm4(uint32_t r[4], uint32_t a) {
    asm volatile("ldmatrix.sync.aligned.m8n8.x4.shared.b16 {%0,%1,%2,%3}, [%4];"
                 : "=r"(r[0]), "=r"(r[1]), "=r"(r[2]), "=r"(r[3]) : "r"(a));
}
__device__ __forceinline__ void mma16816(float c[4], const uint32_t a[4], const uint32_t b[2]) {
    asm volatile("mma.sync.aligned.m16n8k16.row.col.f32.bf16.bf16.f32 "
                 "{%0,%1,%2,%3}, {%4,%5,%6,%7}, {%8,%9}, {%0,%1,%2,%3};"
                 : "+f"(c[0]), "+f"(c[1]), "+f"(c[2]), "+f"(c[3])
                 : "r"(a[0]), "r"(a[1]), "r"(a[2]), "r"(a[3]), "r"(b[0]), "r"(b[1]));
}

// ====================== split-bf16 HMMA GEMM core ===========================
// C[M,N] = (Ah+Al)[M,K] * (Bh+Bl)[N,K]^T   (all K-major bf16)
// CTA tile 128x128xBK32, 128 threads, 4 warps of 64x64, 2 CTAs/SM.
// XOR chunk swizzle on 64B rows: phys_chunk = c ^ ((row>>1)&3).
// LSU de-burst: next-stage cp.async issued BETWEEN the two k16 half-steps so
// the post-barrier LSU path serves only the 16 LDSM feeding the tensor pipe.
constexpr int ROW_B  = 64;
constexpr int COMP_B = 128 * ROW_B;   // 8192 B per component tile
constexpr int STG_B  = 4 * COMP_B;    // 32768 B (Ah,Al,Bh,Bl)
constexpr int NSTG   = 3;
constexpr int SMEM_SZ = NSTG * STG_B; // 98304 B -> 2 CTAs/SM
constexpr int TPAD   = 133;           // fp32 transpose-buffer row stride (words)

__device__ __forceinline__ void load_stage(uint32_t base,
    const bf16* __restrict__ ah, const bf16* __restrict__ al,
    const bf16* __restrict__ bh, const bf16* __restrict__ bl,
    int bm, int bn, int kt, int K, int tid)
{
    const int r  = tid >> 2;
    const int c  = tid & 3;
    const int kc = kt * 32 + c * 8;
    const int cp = c ^ ((r >> 1) & 3);
#pragma unroll
    for (int g = 0; g < 4; g++) {
        const int row = r + g * 32;
        const uint32_t so = (uint32_t)row * ROW_B + cp * 16;
        const long ga = (long)(bm + row) * K + kc;
        const long gb = (long)(bn + row) * K + kc;
        cp16(base + so,              ah + ga);
        cp16(base + COMP_B + so,     al + ga);
        cp16(base + 2 * COMP_B + so, bh + gb);
        cp16(base + 3 * COMP_B + so, bl + gb);
    }
}

// epi: 0 = fp32 C @ coff; 1 = split digits Ch/Cl @ coff;
//      2 = V^T transposed split (batch derived from bm)
__device__ __forceinline__ void gemm_core(
    uint32_t sb, float* __restrict__ tsbuf, int tid,
    const bf16* __restrict__ Ah, const bf16* __restrict__ Al,
    const bf16* __restrict__ Bh, const bf16* __restrict__ Bl,
    int bm, int bn, int N, int K,
    int epi, float* __restrict__ C,
    bf16* __restrict__ Ch, bf16* __restrict__ Cl, long coff)
{
    const int lane = tid & 31, warp = tid >> 5;
    const int wm = warp >> 1, wn = warp & 1;
    const int nk = K >> 5;

    const uint32_t aRow = (uint32_t)(wm * 64 + (lane & 15));
    const uint32_t aSw  = (aRow >> 1) & 3;
    const uint32_t aC0  = (uint32_t)((lane >> 4) & 1);
    const uint32_t bRow0 = (uint32_t)((lane & 7) | (((lane >> 4) & 1) << 3));
    const uint32_t bRow = (uint32_t)(wn * 64) + bRow0;
    const uint32_t bSw  = (bRow0 >> 1) & 3;
    const uint32_t bC0  = (uint32_t)((lane >> 3) & 1);

    float acc[4][8][4];
#pragma unroll
    for (int i = 0; i < 4; i++)
#pragma unroll
        for (int j = 0; j < 8; j++)
#pragma unroll
            for (int q = 0; q < 4; q++) acc[i][j][q] = 0.0f;

#pragma unroll
    for (int s = 0; s < NSTG - 1; s++) {
        load_stage(sb + s * STG_B, Ah, Al, Bh, Bl, bm, bn, s, K, tid);
        CP_COMMIT();
    }

    for (int kt = 0; kt < nk; kt++) {
        CP_WAIT(NSTG - 2);
        __syncthreads();

        const uint32_t st = sb + (kt % NSTG) * STG_B;
        const int nx = kt + NSTG - 1;

        // ---- k16 = 0: fragments + MMAs (tensor refills immediately) ----
        {
            const uint32_t aCk = (aC0) ^ aSw;
            const uint32_t bCk = (bC0) ^ bSw;
            const uint32_t aAddr = st + aRow * ROW_B + aCk * 16;
            const uint32_t bAddr = st + 2 * COMP_B + bRow * ROW_B + bCk * 16;
            uint32_t ah[4][4], al[4][4], bh[4][4], bl[4][4];
#pragma unroll
            for (int mi = 0; mi < 4; mi++) {
                ldm4(ah[mi], aAddr + mi * 16 * ROW_B);
                ldm4(al[mi], aAddr + COMP_B + mi * 16 * ROW_B);
            }
#pragma unroll
            for (int nb = 0; nb < 4; nb++) {
                ldm4(bh[nb], bAddr + nb * 16 * ROW_B);
                ldm4(bl[nb], bAddr + COMP_B + nb * 16 * ROW_B);
            }
#pragma unroll
            for (int mi = 0; mi < 4; mi++)
#pragma unroll
                for (int ni = 0; ni < 8; ni++) {
                    const uint32_t* bhp = &bh[ni >> 1][(ni & 1) * 2];
                    const uint32_t* blp = &bl[ni >> 1][(ni & 1) * 2];
                    mma16816(acc[mi][ni], ah[mi], bhp);
                    mma16816(acc[mi][ni], ah[mi], blp);
                    mma16816(acc[mi][ni], al[mi], bhp);
                }
        }

        // ---- issue next-stage loads mid-iteration (target slot != read slot) ----
        if (nx < nk)
            load_stage(sb + (nx % NSTG) * STG_B, Ah, Al, Bh, Bl, bm, bn, nx, K, tid);
        CP_COMMIT();   // unconditional: exact group accounting

        // ---- k16 = 1 ----
        {
            const uint32_t aCk = (2u + aC0) ^ aSw;
            const uint32_t bCk = (2u + bC0) ^ bSw;
            const uint32_t aAddr = st + aRow * ROW_B + aCk * 16;
            const uint32_t bAddr = st + 2 * COMP_B + bRow * ROW_B + bCk * 16;
            uint32_t ah[4][4], al[4][4], bh[4][4], bl[4][4];
#pragma unroll
            for (int mi = 0; mi < 4; mi++) {
                ldm4(ah[mi], aAddr + mi * 16 * ROW_B);
                ldm4(al[mi], aAddr + COMP_B + mi * 16 * ROW_B);
            }
#pragma unroll
            for (int nb = 0; nb < 4; nb++) {
                ldm4(bh[nb], bAddr + nb * 16 * ROW_B);
                ldm4(bl[nb], bAddr + COMP_B + nb * 16 * ROW_B);
            }
#pragma unroll
            for (int mi = 0; mi < 4; mi++)
#pragma unroll
                for (int ni = 0; ni < 8; ni++) {
                    const uint32_t* bhp = &bh[ni >> 1][(ni & 1) * 2];
                    const uint32_t* blp = &bl[ni >> 1][(ni & 1) * 2];
                    mma16816(acc[mi][ni], ah[mi], bhp);
                    mma16816(acc[mi][ni], ah[mi], blp);
                    mma16816(acc[mi][ni], al[mi], bhp);
                }
        }
    }

    const int qr = lane >> 2, qc = (lane & 3) * 2;

    if (epi == 2) {
        // ---- transposed split epilogue (V^T digits) ----
        __syncthreads();   // all warps done reading the last stage before reuse
#pragma unroll
        for (int mi = 0; mi < 4; mi++)
#pragma unroll
            for (int ni = 0; ni < 8; ni++) {
                const int m = wm * 64 + mi * 16 + qr;
                const int n = wn * 64 + ni * 8 + qc;
                tsbuf[m * TPAD + n]           = acc[mi][ni][0];
                tsbuf[m * TPAD + n + 1]       = acc[mi][ni][1];
                tsbuf[(m + 8) * TPAD + n]     = acc[mi][ni][2];
                tsbuf[(m + 8) * TPAD + n + 1] = acc[mi][ni][3];
            }
        __syncthreads();
        const long DS = (long)D_DIM * S_LEN;
        const int zb = bm >> 11;
        const int mloc = bm & 2047;
        bf16* oh = Ch + (long)zb * DS;
        bf16* ol = Cl + (long)zb * DS;
        for (int k = 0; k < 32; k++) {
            const int n = warp + 4 * k;
            const long base = (long)(bn + n) * S_LEN + mloc;
#pragma unroll
            for (int j = 0; j < 4; j++) {
                const int m = lane + 32 * j;
                float f = tsbuf[m * TPAD + n];
                bf16 h = __float2bfloat16(f);
                oh[base + m] = h;
                ol[base + m] = __float2bfloat16(f - __bfloat162float(h));
            }
        }
        return;
    }

#pragma unroll
    for (int mi = 0; mi < 4; mi++)
#pragma unroll
        for (int ni = 0; ni < 8; ni++) {
            const int m = bm + wm * 64 + mi * 16 + qr;
            const int n = bn + wn * 64 + ni * 8 + qc;
            const long o0 = coff + (long)m * N + n;
            const long o1 = o0 + 8L * N;
            if (epi == 0) {
                *(float2*)(C + o0) = make_float2(acc[mi][ni][0], acc[mi][ni][1]);
                *(float2*)(C + o1) = make_float2(acc[mi][ni][2], acc[mi][ni][3]);
            } else {
                float x0 = acc[mi][ni][0], y0 = acc[mi][ni][1];
                float x1 = acc[mi][ni][2], y1 = acc[mi][ni][3];
                bf16 hx0 = __float2bfloat16(x0), hy0 = __float2bfloat16(y0);
                bf16 hx1 = __float2bfloat16(x1), hy1 = __float2bfloat16(y1);
                *(__nv_bfloat162*)(Ch + o0) = __nv_bfloat162(hx0, hy0);
                *(__nv_bfloat162*)(Ch + o1) = __nv_bfloat162(hx1, hy1);
                *(__nv_bfloat162*)(Cl + o0) = __nv_bfloat162(
                    __float2bfloat16(x0 - __bfloat162float(hx0)),
                    __float2bfloat16(y0 - __bfloat162float(hy0)));
                *(__nv_bfloat162*)(Cl + o1) = __nv_bfloat162(
                    __float2bfloat16(x1 - __bfloat162float(hx1)),
                    __float2bfloat16(y1 - __bfloat162float(hy1)));
            }
        }
}

// batched GEMM over blockIdx.{x,y,z}
template <bool SPLIT>
__global__ void __launch_bounds__(128, 2)
gemm_b(const bf16* __restrict__ Agh, const bf16* __restrict__ Agl,
       const bf16* __restrict__ Bgh, const bf16* __restrict__ Bgl,
       float* __restrict__ C, bf16* __restrict__ Ch, bf16* __restrict__ Cl,
       int N, int K, long sA, long sB, long sC)
{
    extern __shared__ __align__(128) char smem[];
    const int z = blockIdx.z;
    gemm_core(smem_u32(smem), (float*)smem, threadIdx.x,
              Agh + (long)z * sA, Agl + (long)z * sA,
              Bgh + (long)z * sB, Bgl + (long)z * sB,
              blockIdx.y * 128, blockIdx.x * 128, N, K,
              SPLIT ? 1 : 0, C, Ch, Cl, (long)z * sC);
}

// combined launch: jobs [0,512) = V projection -> V^T digits (transposed epi),
//                  jobs [512,576) = M' = Wk * Wq^T -> split digits
__global__ void __launch_bounds__(128, 2)
gemm_vm(const bf16* __restrict__ xh, const bf16* __restrict__ xl,
        const bf16* __restrict__ wvth, const bf16* __restrict__ wvtl,
        const bf16* __restrict__ wkh, const bf16* __restrict__ wkl,
        const bf16* __restrict__ wqh, const bf16* __restrict__ wql,
        bf16* __restrict__ Vth, bf16* __restrict__ Vtl,
        bf16* __restrict__ Mh, bf16* __restrict__ Ml)
{
    extern __shared__ __align__(128) char smem[];
    const int job = blockIdx.x;
    if (job < 512) {
        const int bm = (job >> 3) * 128, bn = (job & 7) * 128;
        gemm_core(smem_u32(smem), (float*)smem, threadIdx.x,
                  xh, xl, wvth, wvtl, bm, bn, D_DIM, D_DIM,
                  2, nullptr, Vth, Vtl, 0);
    } else {
        const int j = job - 512;
        const int bm = (j >> 3) * 128, bn = (j & 7) * 128;
        gemm_core(smem_u32(smem), (float*)smem, threadIdx.x,
                  wkh, wkl, wqh, wql, bm, bn, D_DIM, D_DIM,
                  1, nullptr, Mh, Ml, 0);
    }
}

// =========================== prep kernels ===================================
__global__ void split_f32(const float* __restrict__ in, bf16* __restrict__ oh,
                          bf16* __restrict__ ol)
{
    long i = ((long)blockIdx.x * 256 + threadIdx.x) * 4;
    float4 f = *(const float4*)(in + i);
    bf16 h0 = __float2bfloat16(f.x), h1 = __float2bfloat16(f.y);
    bf16 h2 = __float2bfloat16(f.z), h3 = __float2bfloat16(f.w);
    __nv_bfloat162* hp = (__nv_bfloat162*)(oh + i);
    __nv_bfloat162* lp = (__nv_bfloat162*)(ol + i);
    hp[0] = __nv_bfloat162(h0, h1);
    hp[1] = __nv_bfloat162(h2, h3);
    lp[0] = __nv_bfloat162(__float2bfloat16(f.x - __bfloat162float(h0)),
                           __float2bfloat16(f.y - __bfloat162float(h1)));
    lp[1] = __nv_bfloat162(__float2bfloat16(f.z - __bfloat162float(h2)),
                           __float2bfloat16(f.w - __bfloat162float(h3)));
}

// fused weight prep: z=0 split Wq, z=1 split Wk, z=2 transpose+split Wv
__global__ void prepW(const float* __restrict__ Wq, const float* __restrict__ Wk,
                      const float* __restrict__ Wv,
                      bf16* __restrict__ qh, bf16* __restrict__ ql,
                      bf16* __restrict__ kh, bf16* __restrict__ kl,
                      bf16* __restrict__ vth, bf16* __restrict__ vtl)
{
    __shared__ float t[32][33];
    const int z = blockIdx.z;
    const int bx = blockIdx.x * 32, by = blockIdx.y * 32;
    const int tx = threadIdx.x;
    if (z < 2) {
        const float* ip = (z == 0) ? Wq : Wk;
        bf16* oh = (z == 0) ? qh : kh;
        bf16* ol = (z == 0) ? ql : kl;
#pragma unroll
        for (int i = threadIdx.y; i < 32; i += 8) {
            long o = (long)(by + i) * D_DIM + bx + tx;
            float f = ip[o];
            bf16 h = __float2bfloat16(f);
            oh[o] = h;
            ol[o] = __float2bfloat16(f - __bfloat162float(h));
        }
    } else {
#pragma unroll
        for (int i = threadIdx.y; i < 32; i += 8)
            t[i][tx] = Wv[(long)(by + i) * D_DIM + bx + tx];
        __syncthreads();
#pragma unroll
        for (int i = threadIdx.y; i < 32; i += 8) {
            float f = t[tx][i];
            bf16 h = __float2bfloat16(f);
            long o = (long)(bx + i) * D_DIM + by + tx;
            vth[o] = h;
            vtl[o] = __float2bfloat16(f - __bfloat162float(h));
        }
    }
}

// ============================ softmax =======================================
__device__ __forceinline__ float warpMax(float v) {
#pragma unroll
    for (int o = 16; o; o >>= 1) v = fmaxf(v, __shfl_xor_sync(0xFFFFFFFFu, v, o));
    return v;
}
__device__ __forceinline__ float warpSum(float v) {
#pragma unroll
    for (int o = 16; o; o >>= 1) v += __shfl_xor_sync(0xFFFFFFFFu, v, o);
    return v;
}

struct alignas(8) bf16x4 { __nv_bfloat162 a, b; };

__global__ void softmax_rows(const float* __restrict__ Sc,
                             bf16* __restrict__ Wh, bf16* __restrict__ Wl)
{
    __shared__ float red[8];
    const long row = blockIdx.x;
    const float4* p4 = (const float4*)(Sc + row * (long)S_LEN);
    const int tid = threadIdx.x;
    const float scale = 0.03125f;  // 1/sqrt(1024)

    float4 va = p4[tid], vb = p4[tid + 256];
    float v[8] = {va.x, va.y, va.z, va.w, vb.x, vb.y, vb.z, vb.w};
    float mx = -3.402823e38f;
#pragma unroll
    for (int i = 0; i < 8; i++) { v[i] *= scale; mx = fmaxf(mx, v[i]); }
    mx = warpMax(mx);
    if ((tid & 31) == 0) red[tid >> 5] = mx;
    __syncthreads();
    if (tid < 32) {
        float m = (tid < 8) ? red[tid] : -3.402823e38f;
        m = warpMax(m);
        if (tid == 0) red[0] = m;
    }
    __syncthreads();
    mx = red[0];
    __syncthreads();

    float s = 0.0f;
#pragma unroll
    for (int i = 0; i < 8; i++) { v[i] = __expf(v[i] - mx); s += v[i]; }
    s = warpSum(s);
    if ((tid & 31) == 0) red[tid >> 5] = s;
    __syncthreads();
    if (tid < 32) {
        float t = (tid < 8) ? red[tid] : 0.0f;
        t = warpSum(t);
        if (tid == 0) red[0] = t;
    }
    __syncthreads();
    const float inv = 1.0f / red[0];

    bf16 h[8], l[8];
#pragma unroll
    for (int i = 0; i < 8; i++) {
        float w = v[i] * inv;
        h[i] = __float2bfloat16(w);
        l[i] = __float2bfloat16(w - __bfloat162float(h[i]));
    }
    bf16x4* wh4 = (bf16x4*)(Wh + row * (long)S_LEN);
    bf16x4* wl4 = (bf16x4*)(Wl + row * (long)S_LEN);
    wh4[tid]       = {__nv_bfloat162(h[0], h[1]), __nv_bfloat162(h[2], h[3])};
    wh4[tid + 256] = {__nv_bfloat162(h[4], h[5]), __nv_bfloat162(h[6], h[7])};
    wl4[tid]       = {__nv_bfloat162(l[0], l[1]), __nv_bfloat162(l[2], l[3])};
    wl4[tid + 256] = {__nv_bfloat162(l[4], l[5]), __nv_bfloat162(l[6], l[7])};
}

// ============================ host side =====================================
extern "C" void kernel_launch(void* const* d_in, const int* in_sizes, int n_in,
                              void* d_out, int out_size)
{
    const float* x  = (const float*)d_in[0];
    const float* Wq = (const float*)d_in[1];
    const float* Wk = (const float*)d_in[2];
    const float* Wv = (const float*)d_in[3];
    float* out = (float*)d_out;

    void *xh, *xl, *wqh, *wql, *wkh, *wkl, *wvth, *wvtl, *mh, *ml, *th, *tl;
    void *vth, *vtl, *sc, *wh, *wl;
    cudaGetSymbolAddress(&xh, g_xh);     cudaGetSymbolAddress(&xl, g_xl);
    cudaGetSymbolAddress(&wqh, g_wqh);   cudaGetSymbolAddress(&wql, g_wql);
    cudaGetSymbolAddress(&wkh, g_wkh);   cudaGetSymbolAddress(&wkl, g_wkl);
    cudaGetSymbolAddress(&wvth, g_wvth); cudaGetSymbolAddress(&wvtl, g_wvtl);
    cudaGetSymbolAddress(&mh, g_mh);     cudaGetSymbolAddress(&ml, g_ml);
    cudaGetSymbolAddress(&th, g_th);     cudaGetSymbolAddress(&tl, g_tl);
    cudaGetSymbolAddress(&vth, g_vth);   cudaGetSymbolAddress(&vtl, g_vtl);
    cudaGetSymbolAddress(&sc, g_sc);
    cudaGetSymbolAddress(&wh, g_wh);     cudaGetSymbolAddress(&wl, g_wl);

    cudaFuncSetAttribute(gemm_b<false>, cudaFuncAttributeMaxDynamicSharedMemorySize, SMEM_SZ);
    cudaFuncSetAttribute(gemm_b<true>,  cudaFuncAttributeMaxDynamicSharedMemorySize, SMEM_SZ);
    cudaFuncSetAttribute(gemm_vm,       cudaFuncAttributeMaxDynamicSharedMemorySize, SMEM_SZ);

    const long SD = (long)S_LEN * D_DIM, SS = (long)S_LEN * S_LEN;
    dim3 tb(32, 8);

    // ---- data prep ----
    split_f32<<<(int)((long)MTOT * D_DIM / 1024), 256>>>(x, (bf16*)xh, (bf16*)xl);
    prepW<<<dim3(32, 32, 3), tb>>>(Wq, Wk, Wv,
        (bf16*)wqh, (bf16*)wql, (bf16*)wkh, (bf16*)wkl, (bf16*)wvth, (bf16*)wvtl);

    // ---- combined: V^T digits (transposed epilogue)  +  M' = Wk Wq^T ----
    gemm_vm<<<576, 128, SMEM_SZ>>>((bf16*)xh, (bf16*)xl, (bf16*)wvth, (bf16*)wvtl,
                                   (bf16*)wkh, (bf16*)wkl, (bf16*)wqh, (bf16*)wql,
                                   (bf16*)vth, (bf16*)vtl, (bf16*)mh, (bf16*)ml);

    // ---- T = x M'^T (split digits) ----
    gemm_b<true><<<dim3(D_DIM / 128, MTOT / 128, 1), 128, SMEM_SZ>>>(
        (bf16*)xh, (bf16*)xl, (bf16*)mh, (bf16*)ml,
        nullptr, (bf16*)th, (bf16*)tl, D_DIM, D_DIM, 0, 0, 0);

    // ---- scores = T x^T per batch ----
    gemm_b<false><<<dim3(S_LEN / 128, S_LEN / 128, BATCH), 128, SMEM_SZ>>>(
        (bf16*)th, (bf16*)tl, (bf16*)xh, (bf16*)xl,
        (float*)sc, nullptr, nullptr, S_LEN, D_DIM, SD, SD, SS);

    softmax_rows<<<BATCH * S_LEN, 256>>>((const float*)sc, (bf16*)wh, (bf16*)wl);

    // ---- out = softmaxW * V ----
    gemm_b<false><<<dim3(D_DIM / 128, S_LEN / 128, BATCH), 128, SMEM_SZ>>>(
        (bf16*)wh, (bf16*)wl, (bf16*)vth, (bf16*)vtl,
        out, nullptr, nullptr, D_DIM, S_LEN, SS, SD, SD);
}

// round 13
// speedup vs baseline: 3.9117x; 1.0047x over previous
#include <cuda_runtime.h>
#include <cuda_bf16.h>
#include <cstdint>

#define S_LEN 2048
#define D_DIM 1024
#define BATCH 4
#define MTOT  (BATCH * S_LEN)   // 8192

typedef __nv_bfloat16 bf16;

// ============================ device scratch ================================
__device__ bf16  g_xh [(size_t)MTOT * D_DIM];
__device__ bf16  g_xl [(size_t)MTOT * D_DIM];
__device__ bf16  g_wqh[(size_t)D_DIM * D_DIM];   // Wq digits (native layout)
__device__ bf16  g_wql[(size_t)D_DIM * D_DIM];
__device__ bf16  g_wkh[(size_t)D_DIM * D_DIM];   // Wk digits (native layout)
__device__ bf16  g_wkl[(size_t)D_DIM * D_DIM];
__device__ bf16  g_wvth[(size_t)D_DIM * D_DIM];  // Wv^T digits
__device__ bf16  g_wvtl[(size_t)D_DIM * D_DIM];
__device__ bf16  g_mh [(size_t)D_DIM * D_DIM];   // M' = Wk Wq^T digits
__device__ bf16  g_ml [(size_t)D_DIM * D_DIM];
__device__ bf16  g_th [(size_t)MTOT * D_DIM];    // T = x M'^T digits
__device__ bf16  g_tl [(size_t)MTOT * D_DIM];
__device__ bf16  g_vth[(size_t)BATCH * D_DIM * S_LEN];  // V^T digits per batch
__device__ bf16  g_vtl[(size_t)BATCH * D_DIM * S_LEN];
__device__ float g_sc [(size_t)BATCH * S_LEN * S_LEN];
__device__ bf16  g_wh [(size_t)BATCH * S_LEN * S_LEN];
__device__ bf16  g_wl [(size_t)BATCH * S_LEN * S_LEN];

// ============================ PTX helpers ===================================
__device__ __forceinline__ uint32_t smem_u32(const void* p) {
    uint32_t a;
    asm("{ .reg .u64 t; cvta.to.shared.u64 t, %1; cvt.u32.u64 %0, t; }" : "=r"(a) : "l"(p));
    return a;
}
__device__ __forceinline__ void cp16(uint32_t s, const void* g) {
    asm volatile("cp.async.cg.shared.global [%0], [%1], 16;" :: "r"(s), "l"(g) : "memory");
}
#define CP_COMMIT() asm volatile("cp.async.commit_group;" ::: "memory")
#define CP_WAIT(n)  asm volatile("cp.async.wait_group %0;" :: "n"(n) : "memory")

__device__ __forceinline__ void ldm4(uint32_t r[4], uint32_t a) {
    asm volatile("ldmatrix.sync.aligned.m8n8.x4.shared.b16 {%0,%1,%2,%3}, [%4];"
                 : "=r"(r[0]), "=r"(r[1]), "=r"(r[2]), "=r"(r[3]) : "r"(a));
}
__device__ __forceinline__ void mma16816(float c[4], const uint32_t a[4], const uint32_t b[2]) {
    asm volatile("mma.sync.aligned.m16n8k16.row.col.f32.bf16.bf16.f32 "
                 "{%0,%1,%2,%3}, {%4,%5,%6,%7}, {%8,%9}, {%0,%1,%2,%3};"
                 : "+f"(c[0]), "+f"(c[1]), "+f"(c[2]), "+f"(c[3])
                 : "r"(a[0]), "r"(a[1]), "r"(a[2]), "r"(a[3]), "r"(b[0]), "r"(b[1]));
}

// ====================== split-bf16 HMMA GEMM core ===========================
// C[M,N] = (Ah+Al)[M,K] * (Bh+Bl)[N,K]^T   (all K-major bf16)
// CTA tile 128x128xBK32, 128 threads, 4 warps of 64x64, 2 CTAs/SM.
// XOR chunk swizzle on 64B rows: phys_chunk = c ^ ((row>>1)&3).
// cp.async issue split into two 8-op halves, interleaved with the k16 phases.
constexpr int ROW_B  = 64;
constexpr int COMP_B = 128 * ROW_B;   // 8192 B per component tile
constexpr int STG_B  = 4 * COMP_B;    // 32768 B (Ah,Al,Bh,Bl)
constexpr int NSTG   = 3;
constexpr int SMEM_SZ = NSTG * STG_B; // 98304 B -> 2 CTAs/SM
constexpr int TPAD   = 133;           // fp32 transpose-buffer row stride (words)

__device__ __forceinline__ void load_half(uint32_t base,
    const bf16* __restrict__ ah, const bf16* __restrict__ al,
    const bf16* __restrict__ bh, const bf16* __restrict__ bl,
    int bm, int bn, int kt, int K, int tid, int g0)
{
    const int r  = tid >> 2;
    const int c  = tid & 3;
    const int kc = kt * 32 + c * 8;
    const int cp = c ^ ((r >> 1) & 3);
#pragma unroll
    for (int g = g0; g < g0 + 2; g++) {
        const int row = r + g * 32;
        const uint32_t so = (uint32_t)row * ROW_B + cp * 16;
        const long ga = (long)(bm + row) * K + kc;
        const long gb = (long)(bn + row) * K + kc;
        cp16(base + so,              ah + ga);
        cp16(base + COMP_B + so,     al + ga);
        cp16(base + 2 * COMP_B + so, bh + gb);
        cp16(base + 3 * COMP_B + so, bl + gb);
    }
}

// epi: 0 = fp32 C @ coff; 1 = split digits Ch/Cl @ coff;
//      2 = V^T transposed split (batch derived from bm)
__device__ __forceinline__ void gemm_core(
    uint32_t sb, float* __restrict__ tsbuf, int tid,
    const bf16* __restrict__ Ah, const bf16* __restrict__ Al,
    const bf16* __restrict__ Bh, const bf16* __restrict__ Bl,
    int bm, int bn, int N, int K,
    int epi, float* __restrict__ C,
    bf16* __restrict__ Ch, bf16* __restrict__ Cl, long coff)
{
    const int lane = tid & 31, warp = tid >> 5;
    const int wm = warp >> 1, wn = warp & 1;
    const int nk = K >> 5;

    const uint32_t aRow = (uint32_t)(wm * 64 + (lane & 15));
    const uint32_t aSw  = (aRow >> 1) & 3;
    const uint32_t aC0  = (uint32_t)((lane >> 4) & 1);
    const uint32_t bRow0 = (uint32_t)((lane & 7) | (((lane >> 4) & 1) << 3));
    const uint32_t bRow = (uint32_t)(wn * 64) + bRow0;
    const uint32_t bSw  = (bRow0 >> 1) & 3;
    const uint32_t bC0  = (uint32_t)((lane >> 3) & 1);

    float acc[4][8][4];
#pragma unroll
    for (int i = 0; i < 4; i++)
#pragma unroll
        for (int j = 0; j < 8; j++)
#pragma unroll
            for (int q = 0; q < 4; q++) acc[i][j][q] = 0.0f;

#pragma unroll
    for (int s = 0; s < NSTG - 1; s++) {
        load_half(sb + s * STG_B, Ah, Al, Bh, Bl, bm, bn, s, K, tid, 0);
        load_half(sb + s * STG_B, Ah, Al, Bh, Bl, bm, bn, s, K, tid, 2);
        CP_COMMIT();
    }

    for (int kt = 0; kt < nk; kt++) {
        CP_WAIT(NSTG - 2);
        __syncthreads();

        const uint32_t st = sb + (kt % NSTG) * STG_B;
        const int nx = kt + NSTG - 1;
        const uint32_t nslot = sb + (nx % NSTG) * STG_B;
        const bool doLoad = (nx < nk);

        // ---- k16 = 0: fragments + MMAs (tensor refills immediately) ----
        {
            const uint32_t aCk = (aC0) ^ aSw;
            const uint32_t bCk = (bC0) ^ bSw;
            const uint32_t aAddr = st + aRow * ROW_B + aCk * 16;
            const uint32_t bAddr = st + 2 * COMP_B + bRow * ROW_B + bCk * 16;
            uint32_t ah[4][4], al[4][4], bh[4][4], bl[4][4];
#pragma unroll
            for (int mi = 0; mi < 4; mi++) {
                ldm4(ah[mi], aAddr + mi * 16 * ROW_B);
                ldm4(al[mi], aAddr + COMP_B + mi * 16 * ROW_B);
            }
#pragma unroll
            for (int nb = 0; nb < 4; nb++) {
                ldm4(bh[nb], bAddr + nb * 16 * ROW_B);
                ldm4(bl[nb], bAddr + COMP_B + nb * 16 * ROW_B);
            }
#pragma unroll
            for (int mi = 0; mi < 4; mi++)
#pragma unroll
                for (int ni = 0; ni < 8; ni++) {
                    const uint32_t* bhp = &bh[ni >> 1][(ni & 1) * 2];
                    const uint32_t* blp = &bl[ni >> 1][(ni & 1) * 2];
                    mma16816(acc[mi][ni], ah[mi], bhp);
                    mma16816(acc[mi][ni], ah[mi], blp);
                    mma16816(acc[mi][ni], al[mi], bhp);
                }
        }

        // ---- first half of next-stage loads ----
        if (doLoad)
            load_half(nslot, Ah, Al, Bh, Bl, bm, bn, nx, K, tid, 0);

        // ---- k16 = 1 ----
        {
            const uint32_t aCk = (2u + aC0) ^ aSw;
            const uint32_t bCk = (2u + bC0) ^ bSw;
            const uint32_t aAddr = st + aRow * ROW_B + aCk * 16;
            const uint32_t bAddr = st + 2 * COMP_B + bRow * ROW_B + bCk * 16;
            uint32_t ah[4][4], al[4][4], bh[4][4], bl[4][4];
#pragma unroll
            for (int mi = 0; mi < 4; mi++) {
                ldm4(ah[mi], aAddr + mi * 16 * ROW_B);
                ldm4(al[mi], aAddr + COMP_B + mi * 16 * ROW_B);
            }
#pragma unroll
            for (int nb = 0; nb < 4; nb++) {
                ldm4(bh[nb], bAddr + nb * 16 * ROW_B);
                ldm4(bl[nb], bAddr + COMP_B + nb * 16 * ROW_B);
            }

            // ---- second half of next-stage loads + commit ----
            if (doLoad)
                load_half(nslot, Ah, Al, Bh, Bl, bm, bn, nx, K, tid, 2);
            CP_COMMIT();   // unconditional: exact group accounting

#pragma unroll
            for (int mi = 0; mi < 4; mi++)
#pragma unroll
                for (int ni = 0; ni < 8; ni++) {
                    const uint32_t* bhp = &bh[ni >> 1][(ni & 1) * 2];
                    const uint32_t* blp = &bl[ni >> 1][(ni & 1) * 2];
                    mma16816(acc[mi][ni], ah[mi], bhp);
                    mma16816(acc[mi][ni], ah[mi], blp);
                    mma16816(acc[mi][ni], al[mi], bhp);
                }
        }
    }

    const int qr = lane >> 2, qc = (lane & 3) * 2;

    if (epi == 2) {
        // ---- transposed split epilogue (V^T digits) ----
        __syncthreads();   // all warps done reading the last stage before reuse
#pragma unroll
        for (int mi = 0; mi < 4; mi++)
#pragma unroll
            for (int ni = 0; ni < 8; ni++) {
                const int m = wm * 64 + mi * 16 + qr;
                const int n = wn * 64 + ni * 8 + qc;
                tsbuf[m * TPAD + n]           = acc[mi][ni][0];
                tsbuf[m * TPAD + n + 1]       = acc[mi][ni][1];
                tsbuf[(m + 8) * TPAD + n]     = acc[mi][ni][2];
                tsbuf[(m + 8) * TPAD + n + 1] = acc[mi][ni][3];
            }
        __syncthreads();
        const long DS = (long)D_DIM * S_LEN;
        const int zb = bm >> 11;
        const int mloc = bm & 2047;
        bf16* oh = Ch + (long)zb * DS;
        bf16* ol = Cl + (long)zb * DS;
        for (int k = 0; k < 32; k++) {
            const int n = warp + 4 * k;
            const long base = (long)(bn + n) * S_LEN + mloc;
#pragma unroll
            for (int j = 0; j < 4; j++) {
                const int m = lane + 32 * j;
                float f = tsbuf[m * TPAD + n];
                bf16 h = __float2bfloat16(f);
                oh[base + m] = h;
                ol[base + m] = __float2bfloat16(f - __bfloat162float(h));
            }
        }
        return;
    }

#pragma unroll
    for (int mi = 0; mi < 4; mi++)
#pragma unroll
        for (int ni = 0; ni < 8; ni++) {
            const int m = bm + wm * 64 + mi * 16 + qr;
            const int n = bn + wn * 64 + ni * 8 + qc;
            const long o0 = coff + (long)m * N + n;
            const long o1 = o0 + 8L * N;
            if (epi == 0) {
                *(float2*)(C + o0) = make_float2(acc[mi][ni][0], acc[mi][ni][1]);
                *(float2*)(C + o1) = make_float2(acc[mi][ni][2], acc[mi][ni][3]);
            } else {
                float x0 = acc[mi][ni][0], y0 = acc[mi][ni][1];
                float x1 = acc[mi][ni][2], y1 = acc[mi][ni][3];
                bf16 hx0 = __float2bfloat16(x0), hy0 = __float2bfloat16(y0);
                bf16 hx1 = __float2bfloat16(x1), hy1 = __float2bfloat16(y1);
                *(__nv_bfloat162*)(Ch + o0) = __nv_bfloat162(hx0, hy0);
                *(__nv_bfloat162*)(Ch + o1) = __nv_bfloat162(hx1, hy1);
                *(__nv_bfloat162*)(Cl + o0) = __nv_bfloat162(
                    __float2bfloat16(x0 - __bfloat162float(hx0)),
                    __float2bfloat16(y0 - __bfloat162float(hy0)));
                *(__nv_bfloat162*)(Cl + o1) = __nv_bfloat162(
                    __float2bfloat16(x1 - __bfloat162float(hx1)),
                    __float2bfloat16(y1 - __bfloat162float(hy1)));
            }
        }
}

// batched GEMM over blockIdx.{x,y,z}
template <bool SPLIT>
__global__ void __launch_bounds__(128, 2)
gemm_b(const bf16* __restrict__ Agh, const bf16* __restrict__ Agl,
       const bf16* __restrict__ Bgh, const bf16* __restrict__ Bgl,
       float* __restrict__ C, bf16* __restrict__ Ch, bf16* __restrict__ Cl,
       int N, int K, long sA, long sB, long sC)
{
    extern __shared__ __align__(128) char smem[];
    const int z = blockIdx.z;
    gemm_core(smem_u32(smem), (float*)smem, threadIdx.x,
              Agh + (long)z * sA, Agl + (long)z * sA,
              Bgh + (long)z * sB, Bgl + (long)z * sB,
              blockIdx.y * 128, blockIdx.x * 128, N, K,
              SPLIT ? 1 : 0, C, Ch, Cl, (long)z * sC);
}

// combined launch: jobs [0,512) = V projection -> V^T digits (transposed epi),
//                  jobs [512,576) = M' = Wk * Wq^T -> split digits
__global__ void __launch_bounds__(128, 2)
gemm_vm(const bf16* __restrict__ xh, const bf16* __restrict__ xl,
        const bf16* __restrict__ wvth, const bf16* __restrict__ wvtl,
        const bf16* __restrict__ wkh, const bf16* __restrict__ wkl,
        const bf16* __restrict__ wqh, const bf16* __restrict__ wql,
        bf16* __restrict__ Vth, bf16* __restrict__ Vtl,
        bf16* __restrict__ Mh, bf16* __restrict__ Ml)
{
    extern __shared__ __align__(128) char smem[];
    const int job = blockIdx.x;
    if (job < 512) {
        const int bm = (job >> 3) * 128, bn = (job & 7) * 128;
        gemm_core(smem_u32(smem), (float*)smem, threadIdx.x,
                  xh, xl, wvth, wvtl, bm, bn, D_DIM, D_DIM,
                  2, nullptr, Vth, Vtl, 0);
    } else {
        const int j = job - 512;
        const int bm = (j >> 3) * 128, bn = (j & 7) * 128;
        gemm_core(smem_u32(smem), (float*)smem, threadIdx.x,
                  wkh, wkl, wqh, wql, bm, bn, D_DIM, D_DIM,
                  1, nullptr, Mh, Ml, 0);
    }
}

// =========================== fused prep kernel ==============================
// blocks [0, 8192): split x (256 threads x 4 floats each)
// blocks [8192, 11264): weight prep; j = b-8192, z = j/1024 selects Wq/Wk/Wv,
//   r = j%1024 -> 32x32 tile.  z<2: straight split; z=2: transpose+split.
__global__ void __launch_bounds__(256)
prep_all(const float* __restrict__ x, const float* __restrict__ Wq,
         const float* __restrict__ Wk, const float* __restrict__ Wv,
         bf16* __restrict__ xh, bf16* __restrict__ xl,
         bf16* __restrict__ wqh, bf16* __restrict__ wql,
         bf16* __restrict__ wkh, bf16* __restrict__ wkl,
         bf16* __restrict__ wvth, bf16* __restrict__ wvtl)
{
    __shared__ float t[32][33];
    const int b = blockIdx.x;
    if (b < 8192) {
        long i = ((long)b * 256 + threadIdx.x) * 4;
        float4 f = *(const float4*)(x + i);
        bf16 h0 = __float2bfloat16(f.x), h1 = __float2bfloat16(f.y);
        bf16 h2 = __float2bfloat16(f.z), h3 = __float2bfloat16(f.w);
        __nv_bfloat162* hp = (__nv_bfloat162*)(xh + i);
        __nv_bfloat162* lp = (__nv_bfloat162*)(xl + i);
        hp[0] = __nv_bfloat162(h0, h1);
        hp[1] = __nv_bfloat162(h2, h3);
        lp[0] = __nv_bfloat162(__float2bfloat16(f.x - __bfloat162float(h0)),
                               __float2bfloat16(f.y - __bfloat162float(h1)));
        lp[1] = __nv_bfloat162(__float2bfloat16(f.z - __bfloat162float(h2)),
                               __float2bfloat16(f.w - __bfloat162float(h3)));
        return;
    }
    const int j = b - 8192;
    const int z = j >> 10;
    const int r = j & 1023;
    const int bx = (r & 31) * 32, by = (r >> 5) * 32;
    const int tx = threadIdx.x & 31, ty = threadIdx.x >> 5;
    if (z < 2) {
        const float* ip = (z == 0) ? Wq : Wk;
        bf16* oh = (z == 0) ? wqh : wkh;
        bf16* ol = (z == 0) ? wql : wkl;
#pragma unroll
        for (int i = ty; i < 32; i += 8) {
            long o = (long)(by + i) * D_DIM + bx + tx;
            float f = ip[o];
            bf16 h = __float2bfloat16(f);
            oh[o] = h;
            ol[o] = __float2bfloat16(f - __bfloat162float(h));
        }
    } else {
#pragma unroll
        for (int i = ty; i < 32; i += 8)
            t[i][tx] = Wv[(long)(by + i) * D_DIM + bx + tx];
        __syncthreads();
#pragma unroll
        for (int i = ty; i < 32; i += 8) {
            float f = t[tx][i];
            bf16 h = __float2bfloat16(f);
            long o = (long)(bx + i) * D_DIM + by + tx;
            wvth[o] = h;
            wvtl[o] = __float2bfloat16(f - __bfloat162float(h));
        }
    }
}

// ============================ softmax =======================================
__device__ __forceinline__ float warpMax(float v) {
#pragma unroll
    for (int o = 16; o; o >>= 1) v = fmaxf(v, __shfl_xor_sync(0xFFFFFFFFu, v, o));
    return v;
}
__device__ __forceinline__ float warpSum(float v) {
#pragma unroll
    for (int o = 16; o; o >>= 1) v += __shfl_xor_sync(0xFFFFFFFFu, v, o);
    return v;
}

struct alignas(8) bf16x4 { __nv_bfloat162 a, b; };

__global__ void softmax_rows(const float* __restrict__ Sc,
                             bf16* __restrict__ Wh, bf16* __restrict__ Wl)
{
    __shared__ float red[8];
    const long row = blockIdx.x;
    const float4* p4 = (const float4*)(Sc + row * (long)S_LEN);
    const int tid = threadIdx.x;
    const float scale = 0.03125f;  // 1/sqrt(1024)

    float4 va = p4[tid], vb = p4[tid + 256];
    float v[8] = {va.x, va.y, va.z, va.w, vb.x, vb.y, vb.z, vb.w};
    float mx = -3.402823e38f;
#pragma unroll
    for (int i = 0; i < 8; i++) { v[i] *= scale; mx = fmaxf(mx, v[i]); }
    mx = warpMax(mx);
    if ((tid & 31) == 0) red[tid >> 5] = mx;
    __syncthreads();
    if (tid < 32) {
        float m = (tid < 8) ? red[tid] : -3.402823e38f;
        m = warpMax(m);
        if (tid == 0) red[0] = m;
    }
    __syncthreads();
    mx = red[0];
    __syncthreads();

    float s = 0.0f;
#pragma unroll
    for (int i = 0; i < 8; i++) { v[i] = __expf(v[i] - mx); s += v[i]; }
    s = warpSum(s);
    if ((tid & 31) == 0) red[tid >> 5] = s;
    __syncthreads();
    if (tid < 32) {
        float t = (tid < 8) ? red[tid] : 0.0f;
        t = warpSum(t);
        if (tid == 0) red[0] = t;
    }
    __syncthreads();
    const float inv = 1.0f / red[0];

    bf16 h[8], l[8];
#pragma unroll
    for (int i = 0; i < 8; i++) {
        float w = v[i] * inv;
        h[i] = __float2bfloat16(w);
        l[i] = __float2bfloat16(w - __bfloat162float(h[i]));
    }
    bf16x4* wh4 = (bf16x4*)(Wh + row * (long)S_LEN);
    bf16x4* wl4 = (bf16x4*)(Wl + row * (long)S_LEN);
    wh4[tid]       = {__nv_bfloat162(h[0], h[1]), __nv_bfloat162(h[2], h[3])};
    wh4[tid + 256] = {__nv_bfloat162(h[4], h[5]), __nv_bfloat162(h[6], h[7])};
    wl4[tid]       = {__nv_bfloat162(l[0], l[1]), __nv_bfloat162(l[2], l[3])};
    wl4[tid + 256] = {__nv_bfloat162(l[4], l[5]), __nv_bfloat162(l[6], l[7])};
}

// ============================ host side =====================================
extern "C" void kernel_launch(void* const* d_in, const int* in_sizes, int n_in,
                              void* d_out, int out_size)
{
    const float* x  = (const float*)d_in[0];
    const float* Wq = (const float*)d_in[1];
    const float* Wk = (const float*)d_in[2];
    const float* Wv = (const float*)d_in[3];
    float* out = (float*)d_out;

    void *xh, *xl, *wqh, *wql, *wkh, *wkl, *wvth, *wvtl, *mh, *ml, *th, *tl;
    void *vth, *vtl, *sc, *wh, *wl;
    cudaGetSymbolAddress(&xh, g_xh);     cudaGetSymbolAddress(&xl, g_xl);
    cudaGetSymbolAddress(&wqh, g_wqh);   cudaGetSymbolAddress(&wql, g_wql);
    cudaGetSymbolAddress(&wkh, g_wkh);   cudaGetSymbolAddress(&wkl, g_wkl);
    cudaGetSymbolAddress(&wvth, g_wvth); cudaGetSymbolAddress(&wvtl, g_wvtl);
    cudaGetSymbolAddress(&mh, g_mh);     cudaGetSymbolAddress(&ml, g_ml);
    cudaGetSymbolAddress(&th, g_th);     cudaGetSymbolAddress(&tl, g_tl);
    cudaGetSymbolAddress(&vth, g_vth);   cudaGetSymbolAddress(&vtl, g_vtl);
    cudaGetSymbolAddress(&sc, g_sc);
    cudaGetSymbolAddress(&wh, g_wh);     cudaGetSymbolAddress(&wl, g_wl);

    cudaFuncSetAttribute(gemm_b<false>, cudaFuncAttributeMaxDynamicSharedMemorySize, SMEM_SZ);
    cudaFuncSetAttribute(gemm_b<true>,  cudaFuncAttributeMaxDynamicSharedMemorySize, SMEM_SZ);
    cudaFuncSetAttribute(gemm_vm,       cudaFuncAttributeMaxDynamicSharedMemorySize, SMEM_SZ);

    const long SD = (long)S_LEN * D_DIM, SS = (long)S_LEN * S_LEN;

    // ---- fused data prep (x split + all weight digits) ----
    prep_all<<<8192 + 3 * 1024, 256>>>(x, Wq, Wk, Wv,
        (bf16*)xh, (bf16*)xl, (bf16*)wqh, (bf16*)wql,
        (bf16*)wkh, (bf16*)wkl, (bf16*)wvth, (bf16*)wvtl);

    // ---- combined: V^T digits (transposed epilogue)  +  M' = Wk Wq^T ----
    gemm_vm<<<576, 128, SMEM_SZ>>>((bf16*)xh, (bf16*)xl, (bf16*)wvth, (bf16*)wvtl,
                                   (bf16*)wkh, (bf16*)wkl, (bf16*)wqh, (bf16*)wql,
                                   (bf16*)vth, (bf16*)vtl, (bf16*)mh, (bf16*)ml);

    // ---- T = x M'^T (split digits) ----
    gemm_b<true><<<dim3(D_DIM / 128, MTOT / 128, 1), 128, SMEM_SZ>>>(
        (bf16*)xh, (bf16*)xl, (bf16*)mh, (bf16*)ml,
        nullptr, (bf16*)th, (bf16*)tl, D_DIM, D_DIM, 0, 0, 0);

    // ---- scores = T x^T per batch ----
    gemm_b<false><<<dim3(S_LEN / 128, S_LEN / 128, BATCH), 128, SMEM_SZ>>>(
        (bf16*)th, (bf16*)tl, (bf16*)xh, (bf16*)xl,
        (float*)sc, nullptr, nullptr, S_LEN, D_DIM, SD, SD, SS);

    softmax_rows<<<BATCH * S_LEN, 256>>>((const float*)sc, (bf16*)wh, (bf16*)wl);

    // ---- out = softmaxW * V ----
    gemm_b<false><<<dim3(D_DIM / 128, S_LEN / 128, BATCH), 128, SMEM_SZ>>>(
        (bf16*)wh, (bf16*)wl, (bf16*)vth, (bf16*)vtl,
        out, nullptr, nullptr, D_DIM, S_LEN, SS, SD, SD);
}

// round 14
// speedup vs baseline: 4.1093x; 1.0505x over previous
#include <cuda_runtime.h>
#include <cuda_bf16.h>
#include <cstdint>

#define S_LEN 2048
#define D_DIM 1024
#define BATCH 4
#define MTOT  (BATCH * S_LEN)   // 8192

typedef __nv_bfloat16 bf16;

// ============================ device scratch ================================
__device__ bf16  g_xh [(size_t)MTOT * D_DIM];
__device__ bf16  g_xl [(size_t)MTOT * D_DIM];
__device__ bf16  g_wqh[(size_t)D_DIM * D_DIM];   // Wq digits (native layout)
__device__ bf16  g_wql[(size_t)D_DIM * D_DIM];
__device__ bf16  g_wkh[(size_t)D_DIM * D_DIM];   // Wk digits (native layout)
__device__ bf16  g_wkl[(size_t)D_DIM * D_DIM];
__device__ bf16  g_wvth[(size_t)D_DIM * D_DIM];  // Wv^T digits
__device__ bf16  g_wvtl[(size_t)D_DIM * D_DIM];
__device__ bf16  g_mh [(size_t)D_DIM * D_DIM];   // M' = Wk Wq^T digits
__device__ bf16  g_ml [(size_t)D_DIM * D_DIM];
__device__ bf16  g_th [(size_t)MTOT * D_DIM];    // T = x M'^T digits
__device__ bf16  g_tl [(size_t)MTOT * D_DIM];
__device__ bf16  g_vth[(size_t)BATCH * D_DIM * S_LEN];  // V^T digits per batch
__device__ bf16  g_vtl[(size_t)BATCH * D_DIM * S_LEN];
__device__ float g_sc [(size_t)BATCH * S_LEN * S_LEN];
__device__ bf16  g_wh [(size_t)BATCH * S_LEN * S_LEN];
__device__ bf16  g_wl [(size_t)BATCH * S_LEN * S_LEN];

// ============================ PTX helpers ===================================
__device__ __forceinline__ uint32_t smem_u32(const void* p) {
    uint32_t a;
    asm("{ .reg .u64 t; cvta.to.shared.u64 t, %1; cvt.u32.u64 %0, t; }" : "=r"(a) : "l"(p));
    return a;
}
__device__ __forceinline__ void cp16(uint32_t s, const void* g) {
    asm volatile("cp.async.cg.shared.global [%0], [%1], 16;" :: "r"(s), "l"(g) : "memory");
}
#define CP_COMMIT() asm volatile("cp.async.commit_group;" ::: "memory")
#define CP_WAIT(n)  asm volatile("cp.async.wait_group %0;" :: "n"(n) : "memory")

__device__ __forceinline__ void ldm4(uint32_t r[4], uint32_t a) {
    asm volatile("ldmatrix.sync.aligned.m8n8.x4.shared.b16 {%0,%1,%2,%3}, [%4];"
                 : "=r"(r[0]), "=r"(r[1]), "=r"(r[2]), "=r"(r[3]) : "r"(a));
}
__device__ __forceinline__ void mma16816(float c[4], const uint32_t a[4], const uint32_t b[2]) {
    asm volatile("mma.sync.aligned.m16n8k16.row.col.f32.bf16.bf16.f32 "
                 "{%0,%1,%2,%3}, {%4,%5,%6,%7}, {%8,%9}, {%0,%1,%2,%3};"
                 : "+f"(c[0]), "+f"(c[1]), "+f"(c[2]), "+f"(c[3])
                 : "r"(a[0]), "r"(a[1]), "r"(a[2]), "r"(a[3]), "r"(b[0]), "r"(b[1]));
}

// ====================== split-bf16 HMMA GEMM core ===========================
constexpr int ROW_B  = 64;
constexpr int COMP_B = 128 * ROW_B;   // 8192 B per component tile
constexpr int STG_B  = 4 * COMP_B;    // 32768 B (Ah,Al,Bh,Bl)
constexpr int NSTG   = 3;
constexpr int SMEM_SZ = NSTG * STG_B; // 98304 B -> 2 CTAs/SM
constexpr int TPAD   = 133;           // fp32 transpose-buffer row stride (words)

__device__ __forceinline__ void load_half(uint32_t base,
    const bf16* __restrict__ ah, const bf16* __restrict__ al,
    const bf16* __restrict__ bh, const bf16* __restrict__ bl,
    int bm, int bn, int kt, int K, int tid, int g0)
{
    const int r  = tid >> 2;
    const int c  = tid & 3;
    const int kc = kt * 32 + c * 8;
    const int cp = c ^ ((r >> 1) & 3);
#pragma unroll
    for (int g = g0; g < g0 + 2; g++) {
        const int row = r + g * 32;
        const uint32_t so = (uint32_t)row * ROW_B + cp * 16;
        const long ga = (long)(bm + row) * K + kc;
        const long gb = (long)(bn + row) * K + kc;
        cp16(base + so,              ah + ga);
        cp16(base + COMP_B + so,     al + ga);
        cp16(base + 2 * COMP_B + so, bh + gb);
        cp16(base + 3 * COMP_B + so, bl + gb);
    }
}

// epi: 0 = fp32 C @ coff; 1 = split digits Ch/Cl @ coff;
//      2 = V^T transposed split (batch derived from bm)
__device__ __forceinline__ void gemm_core(
    uint32_t sb, float* __restrict__ tsbuf, int tid,
    const bf16* __restrict__ Ah, const bf16* __restrict__ Al,
    const bf16* __restrict__ Bh, const bf16* __restrict__ Bl,
    int bm, int bn, int N, int K,
    int epi, float* __restrict__ C,
    bf16* __restrict__ Ch, bf16* __restrict__ Cl, long coff)
{
    const int lane = tid & 31, warp = tid >> 5;
    const int wm = warp >> 1, wn = warp & 1;
    const int nk = K >> 5;

    const uint32_t aRow = (uint32_t)(wm * 64 + (lane & 15));
    const uint32_t aSw  = (aRow >> 1) & 3;
    const uint32_t aC0  = (uint32_t)((lane >> 4) & 1);
    const uint32_t bRow0 = (uint32_t)((lane & 7) | (((lane >> 4) & 1) << 3));
    const uint32_t bRow = (uint32_t)(wn * 64) + bRow0;
    const uint32_t bSw  = (bRow0 >> 1) & 3;
    const uint32_t bC0  = (uint32_t)((lane >> 3) & 1);

    float acc[4][8][4];
#pragma unroll
    for (int i = 0; i < 4; i++)
#pragma unroll
        for (int j = 0; j < 8; j++)
#pragma unroll
            for (int q = 0; q < 4; q++) acc[i][j][q] = 0.0f;

#pragma unroll
    for (int s = 0; s < NSTG - 1; s++) {
        load_half(sb + s * STG_B, Ah, Al, Bh, Bl, bm, bn, s, K, tid, 0);
        load_half(sb + s * STG_B, Ah, Al, Bh, Bl, bm, bn, s, K, tid, 2);
        CP_COMMIT();
    }

    for (int kt = 0; kt < nk; kt++) {
        CP_WAIT(NSTG - 2);
        __syncthreads();

        const uint32_t st = sb + (kt % NSTG) * STG_B;
        const int nx = kt + NSTG - 1;
        const uint32_t nslot = sb + (nx % NSTG) * STG_B;
        const bool doLoad = (nx < nk);

        // ---- k16 = 0 ----
        {
            const uint32_t aCk = (aC0) ^ aSw;
            const uint32_t bCk = (bC0) ^ bSw;
            const uint32_t aAddr = st + aRow * ROW_B + aCk * 16;
            const uint32_t bAddr = st + 2 * COMP_B + bRow * ROW_B + bCk * 16;
            uint32_t ah[4][4], al[4][4], bh[4][4], bl[4][4];
#pragma unroll
            for (int mi = 0; mi < 4; mi++) {
                ldm4(ah[mi], aAddr + mi * 16 * ROW_B);
                ldm4(al[mi], aAddr + COMP_B + mi * 16 * ROW_B);
            }
#pragma unroll
            for (int nb = 0; nb < 4; nb++) {
                ldm4(bh[nb], bAddr + nb * 16 * ROW_B);
                ldm4(bl[nb], bAddr + COMP_B + nb * 16 * ROW_B);
            }
#pragma unroll
            for (int mi = 0; mi < 4; mi++)
#pragma unroll
                for (int ni = 0; ni < 8; ni++) {
                    const uint32_t* bhp = &bh[ni >> 1][(ni & 1) * 2];
                    const uint32_t* blp = &bl[ni >> 1][(ni & 1) * 2];
                    mma16816(acc[mi][ni], ah[mi], bhp);
                    mma16816(acc[mi][ni], ah[mi], blp);
                    mma16816(acc[mi][ni], al[mi], bhp);
                }
        }

        if (doLoad)
            load_half(nslot, Ah, Al, Bh, Bl, bm, bn, nx, K, tid, 0);

        // ---- k16 = 1 ----
        {
            const uint32_t aCk = (2u + aC0) ^ aSw;
            const uint32_t bCk = (2u + bC0) ^ bSw;
            const uint32_t aAddr = st + aRow * ROW_B + aCk * 16;
            const uint32_t bAddr = st + 2 * COMP_B + bRow * ROW_B + bCk * 16;
            uint32_t ah[4][4], al[4][4], bh[4][4], bl[4][4];
#pragma unroll
            for (int mi = 0; mi < 4; mi++) {
                ldm4(ah[mi], aAddr + mi * 16 * ROW_B);
                ldm4(al[mi], aAddr + COMP_B + mi * 16 * ROW_B);
            }
#pragma unroll
            for (int nb = 0; nb < 4; nb++) {
                ldm4(bh[nb], bAddr + nb * 16 * ROW_B);
                ldm4(bl[nb], bAddr + COMP_B + nb * 16 * ROW_B);
            }

            if (doLoad)
                load_half(nslot, Ah, Al, Bh, Bl, bm, bn, nx, K, tid, 2);
            CP_COMMIT();   // unconditional: exact group accounting

#pragma unroll
            for (int mi = 0; mi < 4; mi++)
#pragma unroll
                for (int ni = 0; ni < 8; ni++) {
                    const uint32_t* bhp = &bh[ni >> 1][(ni & 1) * 2];
                    const uint32_t* blp = &bl[ni >> 1][(ni & 1) * 2];
                    mma16816(acc[mi][ni], ah[mi], bhp);
                    mma16816(acc[mi][ni], ah[mi], blp);
                    mma16816(acc[mi][ni], al[mi], bhp);
                }
        }
    }

    const int qr = lane >> 2, qc = (lane & 3) * 2;

    if (epi == 2) {
        // ---- transposed split epilogue (V^T digits) ----
        __syncthreads();
#pragma unroll
        for (int mi = 0; mi < 4; mi++)
#pragma unroll
            for (int ni = 0; ni < 8; ni++) {
                const int m = wm * 64 + mi * 16 + qr;
                const int n = wn * 64 + ni * 8 + qc;
                tsbuf[m * TPAD + n]           = acc[mi][ni][0];
                tsbuf[m * TPAD + n + 1]       = acc[mi][ni][1];
                tsbuf[(m + 8) * TPAD + n]     = acc[mi][ni][2];
                tsbuf[(m + 8) * TPAD + n + 1] = acc[mi][ni][3];
            }
        __syncthreads();
        const long DS = (long)D_DIM * S_LEN;
        const int zb = bm >> 11;
        const int mloc = bm & 2047;
        bf16* oh = Ch + (long)zb * DS;
        bf16* ol = Cl + (long)zb * DS;
        for (int k = 0; k < 32; k++) {
            const int n = warp + 4 * k;
            const long base = (long)(bn + n) * S_LEN + mloc;
#pragma unroll
            for (int j = 0; j < 4; j++) {
                const int m = lane + 32 * j;
                float f = tsbuf[m * TPAD + n];
                bf16 h = __float2bfloat16(f);
                oh[base + m] = h;
                ol[base + m] = __float2bfloat16(f - __bfloat162float(h));
            }
        }
        return;
    }

#pragma unroll
    for (int mi = 0; mi < 4; mi++)
#pragma unroll
        for (int ni = 0; ni < 8; ni++) {
            const int m = bm + wm * 64 + mi * 16 + qr;
            const int n = bn + wn * 64 + ni * 8 + qc;
            const long o0 = coff + (long)m * N + n;
            const long o1 = o0 + 8L * N;
            if (epi == 0) {
                *(float2*)(C + o0) = make_float2(acc[mi][ni][0], acc[mi][ni][1]);
                *(float2*)(C + o1) = make_float2(acc[mi][ni][2], acc[mi][ni][3]);
            } else {
                float x0 = acc[mi][ni][0], y0 = acc[mi][ni][1];
                float x1 = acc[mi][ni][2], y1 = acc[mi][ni][3];
                bf16 hx0 = __float2bfloat16(x0), hy0 = __float2bfloat16(y0);
                bf16 hx1 = __float2bfloat16(x1), hy1 = __float2bfloat16(y1);
                *(__nv_bfloat162*)(Ch + o0) = __nv_bfloat162(hx0, hy0);
                *(__nv_bfloat162*)(Ch + o1) = __nv_bfloat162(hx1, hy1);
                *(__nv_bfloat162*)(Cl + o0) = __nv_bfloat162(
                    __float2bfloat16(x0 - __bfloat162float(hx0)),
                    __float2bfloat16(y0 - __bfloat162float(hy0)));
                *(__nv_bfloat162*)(Cl + o1) = __nv_bfloat162(
                    __float2bfloat16(x1 - __bfloat162float(hx1)),
                    __float2bfloat16(y1 - __bfloat162float(hy1)));
            }
        }
}

// batched GEMM over blockIdx.{x,y,z} (used for AV)
__global__ void __launch_bounds__(128, 2)
gemm_b(const bf16* __restrict__ Agh, const bf16* __restrict__ Agl,
       const bf16* __restrict__ Bgh, const bf16* __restrict__ Bgl,
       float* __restrict__ C, int N, int K, long sA, long sB, long sC)
{
    extern __shared__ __align__(128) char smem[];
    const int z = blockIdx.z;
    gemm_core(smem_u32(smem), (float*)smem, threadIdx.x,
              Agh + (long)z * sA, Agl + (long)z * sA,
              Bgh + (long)z * sB, Bgl + (long)z * sB,
              blockIdx.y * 128, blockIdx.x * 128, N, K,
              0, C, nullptr, nullptr, (long)z * sC);
}

// ====== tail-filled phase kernels: main op + V-projection filler jobs =======
// MODE 1: main = M' (Wk Wq^T -> digits), 64 jobs (8x8 tiles)
// MODE 2: main = T  (x M'^T -> digits),  512 jobs (64x8)
// MODE 3: main = scores (T x^T -> fp32, batched), 1024 jobs (4 x 16x16)
// Filler blocks [nMain, grid): V job vj = vBase + (b - nMain):
//   x * Wv^T -> V^T digits (transposed epilogue), vj in [0,512), 64x8 tiles.
template <int MODE>
__global__ void __launch_bounds__(128, 2)
gemm_mix(const bf16* __restrict__ xh, const bf16* __restrict__ xl,
         const bf16* __restrict__ wqh, const bf16* __restrict__ wql,
         const bf16* __restrict__ wkh, const bf16* __restrict__ wkl,
         const bf16* __restrict__ wvth, const bf16* __restrict__ wvtl,
         const bf16* __restrict__ mh, const bf16* __restrict__ ml,
         const bf16* __restrict__ th, const bf16* __restrict__ tl,
         bf16* __restrict__ vth, bf16* __restrict__ vtl,
         bf16* __restrict__ outMh, bf16* __restrict__ outMl,
         bf16* __restrict__ outTh, bf16* __restrict__ outTl,
         float* __restrict__ sc,
         int nMain, int vBase)
{
    extern __shared__ __align__(128) char smem[];
    const uint32_t sb = smem_u32(smem);
    float* tsb = (float*)smem;
    const int b = blockIdx.x, tid = threadIdx.x;

    if (b >= nMain) {
        const int vj = vBase + (b - nMain);
        gemm_core(sb, tsb, tid, xh, xl, wvth, wvtl,
                  (vj >> 3) * 128, (vj & 7) * 128, D_DIM, D_DIM,
                  2, nullptr, vth, vtl, 0);
        return;
    }
    if (MODE == 1) {
        gemm_core(sb, tsb, tid, wkh, wkl, wqh, wql,
                  (b >> 3) * 128, (b & 7) * 128, D_DIM, D_DIM,
                  1, nullptr, outMh, outMl, 0);
    } else if (MODE == 2) {
        gemm_core(sb, tsb, tid, xh, xl, mh, ml,
                  (b >> 3) * 128, (b & 7) * 128, D_DIM, D_DIM,
                  1, nullptr, outTh, outTl, 0);
    } else {
        const long SD = (long)S_LEN * D_DIM, SS = (long)S_LEN * S_LEN;
        const int z = b >> 8, r = b & 255;
        gemm_core(sb, tsb, tid, th + (long)z * SD, tl + (long)z * SD,
                  xh + (long)z * SD, xl + (long)z * SD,
                  (r >> 4) * 128, (r & 15) * 128, S_LEN, D_DIM,
                  0, sc, nullptr, nullptr, (long)z * SS);
    }
}

// =========================== fused prep kernel ==============================
__global__ void __launch_bounds__(256)
prep_all(const float* __restrict__ x, const float* __restrict__ Wq,
         const float* __restrict__ Wk, const float* __restrict__ Wv,
         bf16* __restrict__ xh, bf16* __restrict__ xl,
         bf16* __restrict__ wqh, bf16* __restrict__ wql,
         bf16* __restrict__ wkh, bf16* __restrict__ wkl,
         bf16* __restrict__ wvth, bf16* __restrict__ wvtl)
{
    __shared__ float t[32][33];
    const int b = blockIdx.x;
    if (b < 8192) {
        long i = ((long)b * 256 + threadIdx.x) * 4;
        float4 f = *(const float4*)(x + i);
        bf16 h0 = __float2bfloat16(f.x), h1 = __float2bfloat16(f.y);
        bf16 h2 = __float2bfloat16(f.z), h3 = __float2bfloat16(f.w);
        __nv_bfloat162* hp = (__nv_bfloat162*)(xh + i);
        __nv_bfloat162* lp = (__nv_bfloat162*)(xl + i);
        hp[0] = __nv_bfloat162(h0, h1);
        hp[1] = __nv_bfloat162(h2, h3);
        lp[0] = __nv_bfloat162(__float2bfloat16(f.x - __bfloat162float(h0)),
                               __float2bfloat16(f.y - __bfloat162float(h1)));
        lp[1] = __nv_bfloat162(__float2bfloat16(f.z - __bfloat162float(h2)),
                               __float2bfloat16(f.w - __bfloat162float(h3)));
        return;
    }
    const int j = b - 8192;
    const int z = j >> 10;
    const int r = j & 1023;
    const int bx = (r & 31) * 32, by = (r >> 5) * 32;
    const int tx = threadIdx.x & 31, ty = threadIdx.x >> 5;
    if (z < 2) {
        const float* ip = (z == 0) ? Wq : Wk;
        bf16* oh = (z == 0) ? wqh : wkh;
        bf16* ol = (z == 0) ? wql : wkl;
#pragma unroll
        for (int i = ty; i < 32; i += 8) {
            long o = (long)(by + i) * D_DIM + bx + tx;
            float f = ip[o];
            bf16 h = __float2bfloat16(f);
            oh[o] = h;
            ol[o] = __float2bfloat16(f - __bfloat162float(h));
        }
    } else {
#pragma unroll
        for (int i = ty; i < 32; i += 8)
            t[i][tx] = Wv[(long)(by + i) * D_DIM + bx + tx];
        __syncthreads();
#pragma unroll
        for (int i = ty; i < 32; i += 8) {
            float f = t[tx][i];
            bf16 h = __float2bfloat16(f);
            long o = (long)(bx + i) * D_DIM + by + tx;
            wvth[o] = h;
            wvtl[o] = __float2bfloat16(f - __bfloat162float(h));
        }
    }
}

// ============================ softmax =======================================
__device__ __forceinline__ float warpMax(float v) {
#pragma unroll
    for (int o = 16; o; o >>= 1) v = fmaxf(v, __shfl_xor_sync(0xFFFFFFFFu, v, o));
    return v;
}
__device__ __forceinline__ float warpSum(float v) {
#pragma unroll
    for (int o = 16; o; o >>= 1) v += __shfl_xor_sync(0xFFFFFFFFu, v, o);
    return v;
}

struct alignas(8) bf16x4 { __nv_bfloat162 a, b; };

__global__ void softmax_rows(const float* __restrict__ Sc,
                             bf16* __restrict__ Wh, bf16* __restrict__ Wl)
{
    __shared__ float red[8];
    const long row = blockIdx.x;
    const float4* p4 = (const float4*)(Sc + row * (long)S_LEN);
    const int tid = threadIdx.x;
    const float scale = 0.03125f;  // 1/sqrt(1024)

    float4 va = p4[tid], vb = p4[tid + 256];
    float v[8] = {va.x, va.y, va.z, va.w, vb.x, vb.y, vb.z, vb.w};
    float mx = -3.402823e38f;
#pragma unroll
    for (int i = 0; i < 8; i++) { v[i] *= scale; mx = fmaxf(mx, v[i]); }
    mx = warpMax(mx);
    if ((tid & 31) == 0) red[tid >> 5] = mx;
    __syncthreads();
    if (tid < 32) {
        float m = (tid < 8) ? red[tid] : -3.402823e38f;
        m = warpMax(m);
        if (tid == 0) red[0] = m;
    }
    __syncthreads();
    mx = red[0];
    __syncthreads();

    float s = 0.0f;
#pragma unroll
    for (int i = 0; i < 8; i++) { v[i] = __expf(v[i] - mx); s += v[i]; }
    s = warpSum(s);
    if ((tid & 31) == 0) red[tid >> 5] = s;
    __syncthreads();
    if (tid < 32) {
        float t = (tid < 8) ? red[tid] : 0.0f;
        t = warpSum(t);
        if (tid == 0) red[0] = t;
    }
    __syncthreads();
    const float inv = 1.0f / red[0];

    bf16 h[8], l[8];
#pragma unroll
    for (int i = 0; i < 8; i++) {
        float w = v[i] * inv;
        h[i] = __float2bfloat16(w);
        l[i] = __float2bfloat16(w - __bfloat162float(h[i]));
    }
    bf16x4* wh4 = (bf16x4*)(Wh + row * (long)S_LEN);
    bf16x4* wl4 = (bf16x4*)(Wl + row * (long)S_LEN);
    wh4[tid]       = {__nv_bfloat162(h[0], h[1]), __nv_bfloat162(h[2], h[3])};
    wh4[tid + 256] = {__nv_bfloat162(h[4], h[5]), __nv_bfloat162(h[6], h[7])};
    wl4[tid]       = {__nv_bfloat162(l[0], l[1]), __nv_bfloat162(l[2], l[3])};
    wl4[tid + 256] = {__nv_bfloat162(l[4], l[5]), __nv_bfloat162(l[6], l[7])};
}

// ============================ host side =====================================
extern "C" void kernel_launch(void* const* d_in, const int* in_sizes, int n_in,
                              void* d_out, int out_size)
{
    const float* x  = (const float*)d_in[0];
    const float* Wq = (const float*)d_in[1];
    const float* Wk = (const float*)d_in[2];
    const float* Wv = (const float*)d_in[3];
    float* out = (float*)d_out;

    void *xh, *xl, *wqh, *wql, *wkh, *wkl, *wvth, *wvtl, *mh, *ml, *th, *tl;
    void *vth, *vtl, *sc, *wh, *wl;
    cudaGetSymbolAddress(&xh, g_xh);     cudaGetSymbolAddress(&xl, g_xl);
    cudaGetSymbolAddress(&wqh, g_wqh);   cudaGetSymbolAddress(&wql, g_wql);
    cudaGetSymbolAddress(&wkh, g_wkh);   cudaGetSymbolAddress(&wkl, g_wkl);
    cudaGetSymbolAddress(&wvth, g_wvth); cudaGetSymbolAddress(&wvtl, g_wvtl);
    cudaGetSymbolAddress(&mh, g_mh);     cudaGetSymbolAddress(&ml, g_ml);
    cudaGetSymbolAddress(&th, g_th);     cudaGetSymbolAddress(&tl, g_tl);
    cudaGetSymbolAddress(&vth, g_vth);   cudaGetSymbolAddress(&vtl, g_vtl);
    cudaGetSymbolAddress(&sc, g_sc);
    cudaGetSymbolAddress(&wh, g_wh);     cudaGetSymbolAddress(&wl, g_wl);

    cudaFuncSetAttribute(gemm_b,      cudaFuncAttributeMaxDynamicSharedMemorySize, SMEM_SZ);
    cudaFuncSetAttribute(gemm_mix<1>, cudaFuncAttributeMaxDynamicSharedMemorySize, SMEM_SZ);
    cudaFuncSetAttribute(gemm_mix<2>, cudaFuncAttributeMaxDynamicSharedMemorySize, SMEM_SZ);
    cudaFuncSetAttribute(gemm_mix<3>, cudaFuncAttributeMaxDynamicSharedMemorySize, SMEM_SZ);

    // V-job distribution: fill each phase launch to its ceil boundary
    int nsm = 148;
    cudaDeviceGetAttribute(&nsm, cudaDevAttrMultiProcessorCount, 0);
    const int slots = 2 * nsm;
    auto cap = [slots](int jobs) { return ((jobs + slots - 1) / slots) * slots - jobs; };
    int rem = 512;
    int v1 = rem < (slots - 64) ? rem : (slots - 64); rem -= v1;
    int v2 = rem < cap(512)  ? rem : cap(512);        rem -= v2;
    int v3 = rem < cap(1024) ? rem : cap(1024);       rem -= v3;
    v3 += rem;   // leftover (accepts +1 wave on the largest launch)

    const long SD = (long)S_LEN * D_DIM, SS = (long)S_LEN * S_LEN;

    // ---- fused data prep (x split + all weight digits) ----
    prep_all<<<8192 + 3 * 1024, 256>>>(x, Wq, Wk, Wv,
        (bf16*)xh, (bf16*)xl, (bf16*)wqh, (bf16*)wql,
        (bf16*)wkh, (bf16*)wkl, (bf16*)wvth, (bf16*)wvtl);

    // ---- L1: M' (64) + V filler ----
    gemm_mix<1><<<64 + v1, 128, SMEM_SZ>>>(
        (bf16*)xh, (bf16*)xl, (bf16*)wqh, (bf16*)wql, (bf16*)wkh, (bf16*)wkl,
        (bf16*)wvth, (bf16*)wvtl, (bf16*)mh, (bf16*)ml, (bf16*)th, (bf16*)tl,
        (bf16*)vth, (bf16*)vtl, (bf16*)mh, (bf16*)ml, (bf16*)th, (bf16*)tl,
        (float*)sc, 64, 0);

    // ---- L2: T (512) + V filler ----
    gemm_mix<2><<<512 + v2, 128, SMEM_SZ>>>(
        (bf16*)xh, (bf16*)xl, (bf16*)wqh, (bf16*)wql, (bf16*)wkh, (bf16*)wkl,
        (bf16*)wvth, (bf16*)wvtl, (bf16*)mh, (bf16*)ml, (bf16*)th, (bf16*)tl,
        (bf16*)vth, (bf16*)vtl, (bf16*)mh, (bf16*)ml, (bf16*)th, (bf16*)tl,
        (float*)sc, 512, v1);

    // ---- L3: scores (1024) + V filler ----
    gemm_mix<3><<<1024 + v3, 128, SMEM_SZ>>>(
        (bf16*)xh, (bf16*)xl, (bf16*)wqh, (bf16*)wql, (bf16*)wkh, (bf16*)wkl,
        (bf16*)wvth, (bf16*)wvtl, (bf16*)mh, (bf16*)ml, (bf16*)th, (bf16*)tl,
        (bf16*)vth, (bf16*)vtl, (bf16*)mh, (bf16*)ml, (bf16*)th, (bf16*)tl,
        (float*)sc, 1024, v1 + v2);

    softmax_rows<<<BATCH * S_LEN, 256>>>((const float*)sc, (bf16*)wh, (bf16*)wl);

    // ---- AV: out = softmaxW * V ----
    gemm_b<<<dim3(D_DIM / 128, S_LEN / 128, BATCH), 128, SMEM_SZ>>>(
        (bf16*)wh, (bf16*)wl, (bf16*)vth, (bf16*)vtl,
        out, D_DIM, S_LEN, SS, SD, SD);
}